// round 2
// baseline (speedup 1.0000x reference)
#include <cuda_runtime.h>
#include <math.h>

#define B_ 2
#define S_ 2048
#define D_ 1024
#define H_ 16
#define DK_ 64
#define M_ (B_*S_)          // 4096 rows for all GEMMs
#define NEGINF (-1000000000.0f)

// Scratch (allocation-free rule: __device__ globals)
__device__ float g_Qh[B_*H_*S_*DK_];   // [b,h,s,dk]
__device__ float g_Kh[B_*H_*S_*DK_];
__device__ float g_Vh[B_*H_*S_*DK_];
__device__ float g_att[B_*S_*D_];      // [b,s,d] concat attention output

// ---------------------------------------------------------------------------
// GEMM core: C[m,n] = sum_k A[m,k] * W[n,k] + bias[n]   (NT gemm, K = D_ = 1024)
// 128x128 block tile, BK=8, 256 threads, 8x8 per thread (split 4+4).
// REMAP=true scatters n into [b,h,s,dk] head layout.
// ---------------------------------------------------------------------------
template<bool REMAP>
__device__ __forceinline__ void gemm_nt_core(const float* __restrict__ A,
                                             const float* __restrict__ W,
                                             const float* __restrict__ bias,
                                             float* __restrict__ C)
{
    const int K = D_;
    __shared__ float As[8][128];
    __shared__ float Bs[8][128];

    const int tid = threadIdx.x;
    const int tx  = tid & 15;
    const int ty  = tid >> 4;
    const int m0  = blockIdx.y * 128;
    const int n0  = blockIdx.x * 128;

    const int loadRow = tid >> 1;        // 0..127
    const int loadCol = (tid & 1) * 4;   // 0 or 4

    const float* Ap = A + (size_t)(m0 + loadRow) * K + loadCol;
    const float* Wp = W + (size_t)(n0 + loadRow) * K + loadCol;

    float acc[8][8];
    #pragma unroll
    for (int i = 0; i < 8; i++)
        #pragma unroll
        for (int j = 0; j < 8; j++)
            acc[i][j] = 0.0f;

    for (int k0 = 0; k0 < K; k0 += 8) {
        float4 av = *(const float4*)(Ap + k0);
        float4 bv = *(const float4*)(Wp + k0);
        As[loadCol+0][loadRow] = av.x;  As[loadCol+1][loadRow] = av.y;
        As[loadCol+2][loadRow] = av.z;  As[loadCol+3][loadRow] = av.w;
        Bs[loadCol+0][loadRow] = bv.x;  Bs[loadCol+1][loadRow] = bv.y;
        Bs[loadCol+2][loadRow] = bv.z;  Bs[loadCol+3][loadRow] = bv.w;
        __syncthreads();

        #pragma unroll
        for (int kk = 0; kk < 8; kk++) {
            float a[8], b[8];
            *(float4*)&a[0] = *(const float4*)&As[kk][ty*4];
            *(float4*)&a[4] = *(const float4*)&As[kk][ty*4 + 64];
            *(float4*)&b[0] = *(const float4*)&Bs[kk][tx*4];
            *(float4*)&b[4] = *(const float4*)&Bs[kk][tx*4 + 64];
            #pragma unroll
            for (int i = 0; i < 8; i++)
                #pragma unroll
                for (int j = 0; j < 8; j++)
                    acc[i][j] += a[i] * b[j];
        }
        __syncthreads();
    }

    #pragma unroll
    for (int i = 0; i < 8; i++) {
        const int mi = (i < 4) ? (ty*4 + i) : (64 + ty*4 + i - 4);
        const int m  = m0 + mi;
        #pragma unroll
        for (int j = 0; j < 8; j++) {
            const int ni = (j < 4) ? (tx*4 + j) : (64 + tx*4 + j - 4);
            const int n  = n0 + ni;
            const float val = acc[i][j] + bias[n];
            if (REMAP) {
                const int b  = m / S_, s = m % S_;
                const int h  = n / DK_, dk = n % DK_;
                C[(((size_t)b*H_ + h)*S_ + s)*DK_ + dk] = val;
            } else {
                C[(size_t)m * D_ + n] = val;
            }
        }
    }
}

__global__ void __launch_bounds__(256)
qkv_proj_kernel(const float* __restrict__ q, const float* __restrict__ k,
                const float* __restrict__ v,
                const float* __restrict__ Wq, const float* __restrict__ bq,
                const float* __restrict__ Wk, const float* __restrict__ bk,
                const float* __restrict__ Wv, const float* __restrict__ bv)
{
    const int z = blockIdx.z;
    const float* A    = (z == 0) ? q  : (z == 1) ? k  : v;
    const float* W    = (z == 0) ? Wq : (z == 1) ? Wk : Wv;
    const float* bias = (z == 0) ? bq : (z == 1) ? bk : bv;
    float*       C    = (z == 0) ? g_Qh : (z == 1) ? g_Kh : g_Vh;
    gemm_nt_core<true>(A, W, bias, C);
}

__global__ void __launch_bounds__(256)
out_proj_kernel(const float* __restrict__ Wo, const float* __restrict__ bo,
                float* __restrict__ out)
{
    gemm_nt_core<false>(g_att, Wo, bo, out);
}

// ---------------------------------------------------------------------------
// Flash attention, fp32. 64 query rows per block, 64-key tiles, 256 threads.
// Thread (tx,ty) owns a 4x4 patch: rows ty*4.., cols tx*4.. of the 64x64 tile.
// NOTE: reference mask semantics — mask[b, q] masks the QUERY row (broadcast
// over keys). A masked query row => all scores NEG => uniform softmax.
// ---------------------------------------------------------------------------
__global__ void __launch_bounds__(256)
attn_kernel(const int* __restrict__ mask)
{
    extern __shared__ float sm[];
    float* Qs = sm;               // [64][64]  k-major: Qs[k*64 + q]
    float* Ks = Qs + 64*64;       // [64][64]  k-major: Ks[k*64 + kk]
    float* Vs = Ks + 64*64;       // [64][64]  row-major: Vs[kk*64 + d]
    float* Ps = Vs + 64*64;       // [64][65]  padded: Ps[q*65 + kk]

    const int bh = blockIdx.y;            // 0..31
    const int b  = bh / H_;
    const int h  = bh % H_;
    const int q0 = blockIdx.x * 64;

    const float* Qp = g_Qh + (size_t)bh * S_ * DK_;
    const float* Kp = g_Kh + (size_t)bh * S_ * DK_;
    const float* Vp = g_Vh + (size_t)bh * S_ * DK_;
    const int*   mp = mask + b * S_;

    const int tid = threadIdx.x;
    const int tx  = tid & 15;
    const int ty  = tid >> 4;

    // Load Q tile (transposed into k-major)
    for (int i = tid; i < 64*16; i += 256) {
        const int qq = i >> 4;
        const int k4 = (i & 15) * 4;
        float4 val = *(const float4*)&Qp[(size_t)(q0 + qq)*DK_ + k4];
        Qs[(k4+0)*64 + qq] = val.x;  Qs[(k4+1)*64 + qq] = val.y;
        Qs[(k4+2)*64 + qq] = val.z;  Qs[(k4+3)*64 + qq] = val.w;
    }

    // Per-thread row masks (query rows ty*4 .. ty*4+3)
    bool qmasked[4];
    #pragma unroll
    for (int i = 0; i < 4; i++)
        qmasked[i] = (mp[q0 + ty*4 + i] == 0);

    float m_i[4], l_i[4], acc[4][4];
    #pragma unroll
    for (int i = 0; i < 4; i++) {
        m_i[i] = -1e30f;
        l_i[i] = 0.0f;
        #pragma unroll
        for (int j = 0; j < 4; j++) acc[i][j] = 0.0f;
    }

    for (int kt = 0; kt < S_; kt += 64) {
        __syncthreads();   // previous PV done reading Ps/Vs, QK done reading Ks
        for (int i = tid; i < 64*16; i += 256) {
            const int r  = i >> 4;
            const int k4 = (i & 15) * 4;
            float4 kv = *(const float4*)&Kp[(size_t)(kt + r)*DK_ + k4];
            Ks[(k4+0)*64 + r] = kv.x;  Ks[(k4+1)*64 + r] = kv.y;
            Ks[(k4+2)*64 + r] = kv.z;  Ks[(k4+3)*64 + r] = kv.w;
            float4 vv = *(const float4*)&Vp[(size_t)(kt + r)*DK_ + k4];
            *(float4*)&Vs[r*64 + k4] = vv;
        }
        __syncthreads();

        // S = Q K^T for this 64x64 tile
        float s[4][4];
        #pragma unroll
        for (int i = 0; i < 4; i++)
            #pragma unroll
            for (int j = 0; j < 4; j++) s[i][j] = 0.0f;

        #pragma unroll 8
        for (int k = 0; k < DK_; k++) {
            float4 a  = *(const float4*)&Qs[k*64 + ty*4];
            float4 bb = *(const float4*)&Ks[k*64 + tx*4];
            const float ar[4] = {a.x, a.y, a.z, a.w};
            const float br[4] = {bb.x, bb.y, bb.z, bb.w};
            #pragma unroll
            for (int i = 0; i < 4; i++)
                #pragma unroll
                for (int j = 0; j < 4; j++)
                    s[i][j] += ar[i] * br[j];
        }

        // Mask: reference masks QUERY rows (mask[:, None, :, None] over bhqk)
        #pragma unroll
        for (int i = 0; i < 4; i++) {
            if (qmasked[i]) {
                #pragma unroll
                for (int j = 0; j < 4; j++) s[i][j] = NEGINF;
            }
        }

        // Online softmax per row (row group = 16 lanes sharing ty)
        #pragma unroll
        for (int i = 0; i < 4; i++) {
            float rm = fmaxf(fmaxf(s[i][0], s[i][1]), fmaxf(s[i][2], s[i][3]));
            #pragma unroll
            for (int off = 8; off > 0; off >>= 1)
                rm = fmaxf(rm, __shfl_xor_sync(0xffffffffu, rm, off, 16));
            const float mnew  = fmaxf(m_i[i], rm);
            const float alpha = __expf(m_i[i] - mnew);
            float rs = 0.0f;
            #pragma unroll
            for (int j = 0; j < 4; j++) {
                const float p = __expf(s[i][j] - mnew);
                Ps[(ty*4 + i)*65 + tx*4 + j] = p;
                rs += p;
            }
            #pragma unroll
            for (int off = 8; off > 0; off >>= 1)
                rs += __shfl_xor_sync(0xffffffffu, rs, off, 16);
            l_i[i] = l_i[i]*alpha + rs;
            m_i[i] = mnew;
            #pragma unroll
            for (int j = 0; j < 4; j++) acc[i][j] *= alpha;
        }
        __syncthreads();

        // acc += P @ V   (thread owns rows ty*4.., d-cols tx*4..)
        #pragma unroll 8
        for (int kk = 0; kk < 64; kk++) {
            float4 vv = *(const float4*)&Vs[kk*64 + tx*4];
            const float vr[4] = {vv.x, vv.y, vv.z, vv.w};
            #pragma unroll
            for (int i = 0; i < 4; i++) {
                const float p = Ps[(ty*4 + i)*65 + kk];
                #pragma unroll
                for (int j = 0; j < 4; j++)
                    acc[i][j] += p * vr[j];
            }
        }
    }

    // Write concat layout [b, s, h*64 + d]
    #pragma unroll
    for (int i = 0; i < 4; i++) {
        const int qg = q0 + ty*4 + i;
        const float inv = 1.0f / l_i[i];
        float4 o;
        o.x = acc[i][0]*inv; o.y = acc[i][1]*inv;
        o.z = acc[i][2]*inv; o.w = acc[i][3]*inv;
        *(float4*)&g_att[((size_t)(b*S_ + qg))*D_ + h*DK_ + tx*4] = o;
    }
}

// ---------------------------------------------------------------------------
extern "C" void kernel_launch(void* const* d_in, const int* in_sizes, int n_in,
                              void* d_out, int out_size)
{
    const float* q    = (const float*)d_in[0];
    const float* k    = (const float*)d_in[1];
    const float* v    = (const float*)d_in[2];
    const int*   mask = (const int*)  d_in[3];
    const float* Wq   = (const float*)d_in[4];
    const float* bq   = (const float*)d_in[5];
    const float* Wk   = (const float*)d_in[6];
    const float* bk   = (const float*)d_in[7];
    const float* Wv   = (const float*)d_in[8];
    const float* bv   = (const float*)d_in[9];
    const float* Wo   = (const float*)d_in[10];
    const float* bo   = (const float*)d_in[11];
    float* out = (float*)d_out;

    // 1. QKV projections (fused over grid.z)
    qkv_proj_kernel<<<dim3(D_/128, M_/128, 3), 256>>>(q, k, v, Wq, bq, Wk, bk, Wv, bv);

    // 2. Attention
    const size_t attn_smem = (size_t)(64*64*3 + 64*65) * sizeof(float);  // ~65.8 KB
    cudaFuncSetAttribute(attn_kernel, cudaFuncAttributeMaxDynamicSharedMemorySize,
                         (int)attn_smem);
    attn_kernel<<<dim3(S_/64, B_*H_), 256, attn_smem>>>(mask);

    // 3. Output projection
    out_proj_kernel<<<dim3(D_/128, M_/128), 256>>>(Wo, bo, out);
}

// round 6
// speedup vs baseline: 2.7965x; 2.7965x over previous
#include <cuda_runtime.h>
#include <cuda_bf16.h>
#include <cstdint>
#include <math.h>

#define B_ 2
#define S_ 2048
#define D_ 1024
#define H_ 16
#define DK_ 64
#define M_ (B_*S_)
#define NEGINF (-1000000000.0f)

// ---------------------------------------------------------------------------
// Scratch: EXACTLY the R2-proven 64 MiB footprint (4 fp32 arrays).
// ---------------------------------------------------------------------------
__device__ float g_Qh[M_*D_ / 16 * 16];        // [bh][s][dk] = 16 MiB
__device__ float g_Kh[M_*D_];                  // 16 MiB
__device__ float g_Vh[M_*D_];                  // 16 MiB
__device__ float g_att[M_*D_];                 // [m][d] concat, 16 MiB

// ---------------------------------------------------------------------------
// PTX helpers (base sm_100-legal: ldmatrix + mma.sync)
// ---------------------------------------------------------------------------
__device__ __forceinline__ uint32_t smem_u32(const void* p) {
    uint32_t a;
    asm("{ .reg .u64 t; cvta.to.shared.u64 t, %1; cvt.u32.u64 %0, t; }" : "=r"(a) : "l"(p));
    return a;
}
__device__ __forceinline__ void ldsm4(uint32_t* r, uint32_t addr) {
    asm volatile("ldmatrix.sync.aligned.m8n8.x4.shared.b16 {%0,%1,%2,%3}, [%4];"
        : "=r"(r[0]), "=r"(r[1]), "=r"(r[2]), "=r"(r[3]) : "r"(addr));
}
__device__ __forceinline__ void ldsm4_t(uint32_t* r, uint32_t addr) {
    asm volatile("ldmatrix.sync.aligned.m8n8.x4.trans.shared.b16 {%0,%1,%2,%3}, [%4];"
        : "=r"(r[0]), "=r"(r[1]), "=r"(r[2]), "=r"(r[3]) : "r"(addr));
}
__device__ __forceinline__ void mma16816(float* d, const uint32_t* a, const uint32_t* b) {
    asm volatile(
        "mma.sync.aligned.m16n8k16.row.col.f32.bf16.bf16.f32 "
        "{%0,%1,%2,%3}, {%4,%5,%6,%7}, {%8,%9}, {%0,%1,%2,%3};"
        : "+f"(d[0]), "+f"(d[1]), "+f"(d[2]), "+f"(d[3])
        : "r"(a[0]), "r"(a[1]), "r"(a[2]), "r"(a[3]), "r"(b[0]), "r"(b[1]));
}
__device__ __forceinline__ uint32_t packbf(float lo, float hi) {
    uint32_t r;
    asm("cvt.rn.bf16x2.f32 %0, %1, %2;" : "=r"(r) : "f"(hi), "f"(lo));
    return r;
}
__device__ __forceinline__ float bfres(float x) {
    return x - __bfloat162float(__float2bfloat16(x));
}
// float4 -> (hi bf16x4, lo bf16x4) as two uint2
__device__ __forceinline__ void split4(float4 x, uint2& h, uint2& l) {
    h.x = packbf(x.x, x.y);  h.y = packbf(x.z, x.w);
    l.x = packbf(bfres(x.x), bfres(x.y));
    l.y = packbf(bfres(x.z), bfres(x.w));
}

// ---------------------------------------------------------------------------
// Projection GEMM: C[m,n] = sum_k A[m,k]*W[n,k] + bias[n]   (fp32 in/out)
// 128x128 block, BK=64, 8 warps (4m x 2n). Split fp32->hi/lo bf16 in smem load.
// ---------------------------------------------------------------------------
#define PPAD 72
#define PSLAB (128*PPAD)
#define PROJ_SMEM (4*PSLAB*2)

template<int MODE>   // 0: row-major out; 1: remap to [bh][s][dk]
__device__ __forceinline__ void proj_gemm(const float* __restrict__ A,
                                          const float* __restrict__ W,
                                          const float* __restrict__ bias,
                                          float* __restrict__ C)
{
    extern __shared__ __nv_bfloat16 sm[];
    const uint32_t sb = smem_u32(sm);
    const int tid  = threadIdx.x;
    const int lane = tid & 31;
    const int wid  = tid >> 5;
    const int wm   = wid & 3;
    const int wn   = wid >> 2;
    const int m0 = blockIdx.y * 128;
    const int n0 = blockIdx.x * 128;

    float acc[2][8][4];
    #pragma unroll
    for (int mi = 0; mi < 2; mi++)
        #pragma unroll
        for (int nj = 0; nj < 8; nj++)
            #pragma unroll
            for (int e = 0; e < 4; e++) acc[mi][nj][e] = 0.0f;

    for (int c = 0; c < 16; c++) {
        const int k0 = c * 64;
        __syncthreads();
        // A tile: 128 rows x 64 fp32 -> slabs 0 (hi), 1 (lo)
        #pragma unroll
        for (int it = 0; it < 8; it++) {
            const int idx = tid + it*256;        // 0..2047
            const int row = idx >> 4;
            const int v   = idx & 15;
            float4 x = *((const float4*)(A + (size_t)(m0+row)*D_ + k0) + v);
            uint2 h, l; split4(x, h, l);
            *(uint2*)(sm + 0*PSLAB + row*PPAD + v*4) = h;
            *(uint2*)(sm + 1*PSLAB + row*PPAD + v*4) = l;
        }
        // W tile: 128 rows x 64 fp32 -> slabs 2 (hi), 3 (lo)
        #pragma unroll
        for (int it = 0; it < 8; it++) {
            const int idx = tid + it*256;
            const int row = idx >> 4;
            const int v   = idx & 15;
            float4 x = *((const float4*)(W + (size_t)(n0+row)*D_ + k0) + v);
            uint2 h, l; split4(x, h, l);
            *(uint2*)(sm + 2*PSLAB + row*PPAD + v*4) = h;
            *(uint2*)(sm + 3*PSLAB + row*PPAD + v*4) = l;
        }
        __syncthreads();

        #pragma unroll
        for (int kk = 0; kk < 4; kk++) {
            uint32_t ah[2][4], al[2][4];
            #pragma unroll
            for (int mi = 0; mi < 2; mi++) {
                const int r   = wm*32 + mi*16 + (lane & 15);
                const int col = kk*16 + ((lane & 16) ? 8 : 0);
                ldsm4(ah[mi], sb + 2*(0*PSLAB + r*PPAD + col));
                ldsm4(al[mi], sb + 2*(1*PSLAB + r*PPAD + col));
            }
            #pragma unroll
            for (int jp = 0; jp < 4; jp++) {
                const int p   = lane >> 3;
                const int r   = wn*64 + jp*16 + ((p >= 2) ? 8 : 0) + (lane & 7);
                const int col = kk*16 + ((p & 1) ? 8 : 0);
                uint32_t th[4], tl[4];
                ldsm4(th, sb + 2*(2*PSLAB + r*PPAD + col));
                ldsm4(tl, sb + 2*(3*PSLAB + r*PPAD + col));
                #pragma unroll
                for (int mi = 0; mi < 2; mi++) {
                    mma16816(acc[mi][2*jp],   ah[mi], th);
                    mma16816(acc[mi][2*jp],   ah[mi], tl);
                    mma16816(acc[mi][2*jp],   al[mi], th);
                    mma16816(acc[mi][2*jp+1], ah[mi], th+2);
                    mma16816(acc[mi][2*jp+1], ah[mi], tl+2);
                    mma16816(acc[mi][2*jp+1], al[mi], th+2);
                }
            }
        }
    }

    // Epilogue (fp32)
    const int g  = lane >> 2;
    const int cc = lane & 3;
    #pragma unroll
    for (int mi = 0; mi < 2; mi++) {
        const int ra = m0 + wm*32 + mi*16 + g;
        const int rb = ra + 8;
        #pragma unroll
        for (int nj = 0; nj < 8; nj++) {
            const int col = n0 + wn*64 + nj*8 + cc*2;
            const float b0 = bias[col], b1 = bias[col+1];
            const float v00 = acc[mi][nj][0] + b0, v01 = acc[mi][nj][1] + b1;
            const float v10 = acc[mi][nj][2] + b0, v11 = acc[mi][nj][3] + b1;
            if (MODE == 1) {
                const int h = col >> 6, dk = col & 63;
                const int ba = ra >> 11, sa = ra & (S_-1);
                const int bb = rb >> 11, sb2 = rb & (S_-1);
                *(float2*)&C[(((size_t)ba*H_ + h)*S_ + sa)*DK_ + dk] = make_float2(v00, v01);
                *(float2*)&C[(((size_t)bb*H_ + h)*S_ + sb2)*DK_ + dk] = make_float2(v10, v11);
            } else {
                *(float2*)&C[(size_t)ra*D_ + col] = make_float2(v00, v01);
                *(float2*)&C[(size_t)rb*D_ + col] = make_float2(v10, v11);
            }
        }
    }
}

__global__ void __launch_bounds__(256, 1)
qkv_mma_kernel(const float* __restrict__ q, const float* __restrict__ k,
               const float* __restrict__ v,
               const float* __restrict__ Wq, const float* __restrict__ bq,
               const float* __restrict__ Wk, const float* __restrict__ bk,
               const float* __restrict__ Wv, const float* __restrict__ bv)
{
    const int z = blockIdx.z;
    if (z == 0)      proj_gemm<1>(q, Wq, bq, g_Qh);
    else if (z == 1) proj_gemm<1>(k, Wk, bk, g_Kh);
    else             proj_gemm<1>(v, Wv, bv, g_Vh);
}

__global__ void __launch_bounds__(256, 1)
out_mma_kernel(const float* __restrict__ Wo, const float* __restrict__ bo,
               float* __restrict__ out)
{
    proj_gemm<0>(g_att, Wo, bo, out);
}

// ---------------------------------------------------------------------------
// Flash attention on mma.sync. 8 warps x m16 = 128 q rows/block, 64-key tiles.
// fp32 heads in gmem; split to hi/lo bf16 during smem loads.
// Mask semantics: mask[b, q] masks QUERY rows (broadcast over keys).
// ---------------------------------------------------------------------------
#define APAD 72
#define AKV_SLAB (64*APAD)
#define ATT_SMEM (2*128*APAD*2)   // 36864 B (KV region reuses it: 4*64*72*2 = same)

__global__ void __launch_bounds__(256, 1)
attn_mma_kernel(const int* __restrict__ mask)
{
    extern __shared__ __nv_bfloat16 sm[];
    const uint32_t sb = smem_u32(sm);
    const int tid  = threadIdx.x;
    const int lane = tid & 31;
    const int wid  = tid >> 5;
    const int g    = lane >> 2;
    const int cc   = lane & 3;

    const int bh = blockIdx.y;
    const int b  = bh >> 4;
    const int h  = bh & 15;
    const int q0 = blockIdx.x * 128;

    const float* Qp = g_Qh + (size_t)bh*S_*DK_;
    const float* Kp = g_Kh + (size_t)bh*S_*DK_;
    const float* Vp = g_Vh + (size_t)bh*S_*DK_;
    const int* mp = mask + b*S_;

    // ---- load Q tile (128 x 64 fp32 -> hi/lo slabs), extract frags ----
    #pragma unroll
    for (int it = 0; it < 8; it++) {
        const int idx = tid + it*256;    // 0..2047
        const int row = idx >> 4;
        const int v   = idx & 15;
        float4 x = *((const float4*)(Qp + (size_t)(q0+row)*DK_) + v);
        uint2 hh, ll; split4(x, hh, ll);
        *(uint2*)(sm + 0*(128*APAD) + row*APAD + v*4) = hh;
        *(uint2*)(sm + 1*(128*APAD) + row*APAD + v*4) = ll;
    }
    __syncthreads();

    uint32_t qh[4][4], ql[4][4];
    #pragma unroll
    for (int kk = 0; kk < 4; kk++) {
        const int r   = wid*16 + (lane & 15);
        const int col = kk*16 + ((lane & 16) ? 8 : 0);
        ldsm4(qh[kk], sb + 2*(0        + r*APAD + col));
        ldsm4(ql[kk], sb + 2*(128*APAD + r*APAD + col));
    }

    const int qr0 = q0 + wid*16 + g;
    const int qr1 = qr0 + 8;
    const bool msk0 = (mp[qr0] == 0);
    const bool msk1 = (mp[qr1] == 0);

    float mr0 = -1e30f, mr1 = -1e30f, lr0 = 0.0f, lr1 = 0.0f;
    float oacc[8][4];
    #pragma unroll
    for (int nj = 0; nj < 8; nj++)
        #pragma unroll
        for (int e = 0; e < 4; e++) oacc[nj][e] = 0.0f;

    for (int kt = 0; kt < S_; kt += 64) {
        __syncthreads();
        // K tile -> slabs 0 (hi), 1 (lo); V tile -> slabs 2 (hi), 3 (lo)
        #pragma unroll
        for (int it = 0; it < 4; it++) {
            const int idx = tid + it*256;    // 0..1023
            const int row = idx >> 4;
            const int v   = idx & 15;
            float4 x = *((const float4*)(Kp + (size_t)(kt+row)*DK_) + v);
            uint2 hh, ll; split4(x, hh, ll);
            *(uint2*)(sm + 0*AKV_SLAB + row*APAD + v*4) = hh;
            *(uint2*)(sm + 1*AKV_SLAB + row*APAD + v*4) = ll;
        }
        #pragma unroll
        for (int it = 0; it < 4; it++) {
            const int idx = tid + it*256;
            const int row = idx >> 4;
            const int v   = idx & 15;
            float4 x = *((const float4*)(Vp + (size_t)(kt+row)*DK_) + v);
            uint2 hh, ll; split4(x, hh, ll);
            *(uint2*)(sm + 2*AKV_SLAB + row*APAD + v*4) = hh;
            *(uint2*)(sm + 3*AKV_SLAB + row*APAD + v*4) = ll;
        }
        __syncthreads();

        // ---- S = Q K^T (K frags streamed) ----
        float sacc[8][4];
        #pragma unroll
        for (int nj = 0; nj < 8; nj++)
            #pragma unroll
            for (int e = 0; e < 4; e++) sacc[nj][e] = 0.0f;

        #pragma unroll
        for (int kk = 0; kk < 4; kk++) {
            #pragma unroll
            for (int jp = 0; jp < 4; jp++) {
                const int p   = lane >> 3;
                const int r   = jp*16 + ((p >= 2) ? 8 : 0) + (lane & 7);
                const int col = kk*16 + ((p & 1) ? 8 : 0);
                uint32_t th[4], tl[4];
                ldsm4(th, sb + 2*(0*AKV_SLAB + r*APAD + col));
                ldsm4(tl, sb + 2*(1*AKV_SLAB + r*APAD + col));
                mma16816(sacc[2*jp],   qh[kk], th);
                mma16816(sacc[2*jp],   qh[kk], tl);
                mma16816(sacc[2*jp],   ql[kk], th);
                mma16816(sacc[2*jp+1], qh[kk], th+2);
                mma16816(sacc[2*jp+1], qh[kk], tl+2);
                mma16816(sacc[2*jp+1], ql[kk], th+2);
            }
        }

        // ---- mask + online softmax ----
        if (msk0) {
            #pragma unroll
            for (int nj = 0; nj < 8; nj++) { sacc[nj][0] = NEGINF; sacc[nj][1] = NEGINF; }
        }
        if (msk1) {
            #pragma unroll
            for (int nj = 0; nj < 8; nj++) { sacc[nj][2] = NEGINF; sacc[nj][3] = NEGINF; }
        }

        float mx0 = -1e30f, mx1 = -1e30f;
        #pragma unroll
        for (int nj = 0; nj < 8; nj++) {
            mx0 = fmaxf(mx0, fmaxf(sacc[nj][0], sacc[nj][1]));
            mx1 = fmaxf(mx1, fmaxf(sacc[nj][2], sacc[nj][3]));
        }
        mx0 = fmaxf(mx0, __shfl_xor_sync(0xffffffffu, mx0, 1));
        mx0 = fmaxf(mx0, __shfl_xor_sync(0xffffffffu, mx0, 2));
        mx1 = fmaxf(mx1, __shfl_xor_sync(0xffffffffu, mx1, 1));
        mx1 = fmaxf(mx1, __shfl_xor_sync(0xffffffffu, mx1, 2));

        const float mn0 = fmaxf(mr0, mx0);
        const float mn1 = fmaxf(mr1, mx1);
        const float al0 = __expf(mr0 - mn0);
        const float al1 = __expf(mr1 - mn1);
        mr0 = mn0; mr1 = mn1;

        float rs0 = 0.0f, rs1 = 0.0f;
        #pragma unroll
        for (int nj = 0; nj < 8; nj++) {
            const float p0 = __expf(sacc[nj][0] - mn0);
            const float p1 = __expf(sacc[nj][1] - mn0);
            const float p2 = __expf(sacc[nj][2] - mn1);
            const float p3 = __expf(sacc[nj][3] - mn1);
            sacc[nj][0] = p0; sacc[nj][1] = p1; sacc[nj][2] = p2; sacc[nj][3] = p3;
            rs0 += p0 + p1; rs1 += p2 + p3;
        }
        rs0 += __shfl_xor_sync(0xffffffffu, rs0, 1);
        rs0 += __shfl_xor_sync(0xffffffffu, rs0, 2);
        rs1 += __shfl_xor_sync(0xffffffffu, rs1, 1);
        rs1 += __shfl_xor_sync(0xffffffffu, rs1, 2);
        lr0 = lr0*al0 + rs0;
        lr1 = lr1*al1 + rs1;

        #pragma unroll
        for (int nj = 0; nj < 8; nj++) {
            oacc[nj][0] *= al0; oacc[nj][1] *= al0;
            oacc[nj][2] *= al1; oacc[nj][3] *= al1;
        }

        // ---- O += P V (V frags streamed; P split hi + residual) ----
        #pragma unroll
        for (int t = 0; t < 4; t++) {
            const float p00 = sacc[2*t][0],   p01 = sacc[2*t][1];
            const float p02 = sacc[2*t][2],   p03 = sacc[2*t][3];
            const float p10 = sacc[2*t+1][0], p11 = sacc[2*t+1][1];
            const float p12 = sacc[2*t+1][2], p13 = sacc[2*t+1][3];
            uint32_t pa[4], pl[4];
            pa[0] = packbf(p00, p01); pa[1] = packbf(p02, p03);
            pa[2] = packbf(p10, p11); pa[3] = packbf(p12, p13);
            pl[0] = packbf(bfres(p00), bfres(p01)); pl[1] = packbf(bfres(p02), bfres(p03));
            pl[2] = packbf(bfres(p10), bfres(p11)); pl[3] = packbf(bfres(p12), bfres(p13));

            #pragma unroll
            for (int jp = 0; jp < 4; jp++) {
                const int p   = lane >> 3;
                const int r   = t*16 + ((p & 1) ? 8 : 0) + (lane & 7);
                const int col = jp*16 + ((p >= 2) ? 8 : 0);
                uint32_t th[4], tl[4];
                ldsm4_t(th, sb + 2*(2*AKV_SLAB + r*APAD + col));
                ldsm4_t(tl, sb + 2*(3*AKV_SLAB + r*APAD + col));
                mma16816(oacc[2*jp],   pa, th);
                mma16816(oacc[2*jp],   pa, tl);
                mma16816(oacc[2*jp],   pl, th);
                mma16816(oacc[2*jp+1], pa, th+2);
                mma16816(oacc[2*jp+1], pa, tl+2);
                mma16816(oacc[2*jp+1], pl, th+2);
            }
        }
    }

    // ---- epilogue: att = oacc / l, fp32 concat [b,s,h*64+dk] ----
    const float inv0 = 1.0f / lr0;
    const float inv1 = 1.0f / lr1;
    float* outa = g_att + ((size_t)(b*S_ + qr0))*D_ + h*DK_;
    float* outb = g_att + ((size_t)(b*S_ + qr1))*D_ + h*DK_;
    #pragma unroll
    for (int nj = 0; nj < 8; nj++) {
        const int dk = nj*8 + cc*2;
        *(float2*)&outa[dk] = make_float2(oacc[nj][0]*inv0, oacc[nj][1]*inv0);
        *(float2*)&outb[dk] = make_float2(oacc[nj][2]*inv1, oacc[nj][3]*inv1);
    }
}

// ---------------------------------------------------------------------------
extern "C" void kernel_launch(void* const* d_in, const int* in_sizes, int n_in,
                              void* d_out, int out_size)
{
    const float* q    = (const float*)d_in[0];
    const float* k    = (const float*)d_in[1];
    const float* v    = (const float*)d_in[2];
    const int*   mask = (const int*)  d_in[3];
    const float* Wq   = (const float*)d_in[4];
    const float* bq   = (const float*)d_in[5];
    const float* Wk   = (const float*)d_in[6];
    const float* bk   = (const float*)d_in[7];
    const float* Wv   = (const float*)d_in[8];
    const float* bv   = (const float*)d_in[9];
    const float* Wo   = (const float*)d_in[10];
    const float* bo   = (const float*)d_in[11];
    float* out = (float*)d_out;

    static int configured = 0;
    if (!configured) {
        cudaFuncSetAttribute(qkv_mma_kernel, cudaFuncAttributeMaxDynamicSharedMemorySize, PROJ_SMEM);
        cudaFuncSetAttribute(out_mma_kernel, cudaFuncAttributeMaxDynamicSharedMemorySize, PROJ_SMEM);
        configured = 1;
    }

    // 1. QKV projections (mma.sync split-bf16, split done in smem load)
    qkv_mma_kernel<<<dim3(D_/128, M_/128, 3), 256, PROJ_SMEM>>>(
        q, k, v, Wq, bq, Wk, bk, Wv, bv);

    // 2. Attention (mma.sync flash, fp32 heads)
    attn_mma_kernel<<<dim3(S_/128, B_*H_), 256, ATT_SMEM>>>(mask);

    // 3. Output projection
    out_mma_kernel<<<dim3(D_/128, M_/128), 256, PROJ_SMEM>>>(Wo, bo, out);
}

// round 7
// speedup vs baseline: 3.1184x; 1.1151x over previous
#include <cuda_runtime.h>
#include <cuda_bf16.h>
#include <cstdint>
#include <math.h>

#define B_ 2
#define S_ 2048
#define D_ 1024
#define H_ 16
#define DK_ 64
#define M_ (B_*S_)
#define NEGINF (-1000000000.0f)

// ---------------------------------------------------------------------------
// Scratch: 64 MiB proven-safe footprint
// ---------------------------------------------------------------------------
__device__ float g_Qh[M_*D_];
__device__ float g_Kh[M_*D_];
__device__ float g_Vh[M_*D_];
__device__ float g_att[M_*D_];

// ---------------------------------------------------------------------------
// PTX helpers (base sm_100-legal: ldmatrix + mma.sync)
// ---------------------------------------------------------------------------
__device__ __forceinline__ uint32_t smem_u32(const void* p) {
    uint32_t a;
    asm("{ .reg .u64 t; cvta.to.shared.u64 t, %1; cvt.u32.u64 %0, t; }" : "=r"(a) : "l"(p));
    return a;
}
__device__ __forceinline__ void ldsm4(uint32_t* r, uint32_t addr) {
    asm volatile("ldmatrix.sync.aligned.m8n8.x4.shared.b16 {%0,%1,%2,%3}, [%4];"
        : "=r"(r[0]), "=r"(r[1]), "=r"(r[2]), "=r"(r[3]) : "r"(addr));
}
__device__ __forceinline__ void ldsm4_t(uint32_t* r, uint32_t addr) {
    asm volatile("ldmatrix.sync.aligned.m8n8.x4.trans.shared.b16 {%0,%1,%2,%3}, [%4];"
        : "=r"(r[0]), "=r"(r[1]), "=r"(r[2]), "=r"(r[3]) : "r"(addr));
}
__device__ __forceinline__ void mma16816(float* d, const uint32_t* a, const uint32_t* b) {
    asm volatile(
        "mma.sync.aligned.m16n8k16.row.col.f32.bf16.bf16.f32 "
        "{%0,%1,%2,%3}, {%4,%5,%6,%7}, {%8,%9}, {%0,%1,%2,%3};"
        : "+f"(d[0]), "+f"(d[1]), "+f"(d[2]), "+f"(d[3])
        : "r"(a[0]), "r"(a[1]), "r"(a[2]), "r"(a[3]), "r"(b[0]), "r"(b[1]));
}
__device__ __forceinline__ uint32_t packbf(float lo, float hi) {
    uint32_t r;
    asm("cvt.rn.bf16x2.f32 %0, %1, %2;" : "=r"(r) : "f"(hi), "f"(lo));
    return r;
}
__device__ __forceinline__ float bfres(float x) {
    return x - __bfloat162float(__float2bfloat16(x));
}
__device__ __forceinline__ void split4(float4 x, uint2& h, uint2& l) {
    h.x = packbf(x.x, x.y);  h.y = packbf(x.z, x.w);
    l.x = packbf(bfres(x.x), bfres(x.y));
    l.y = packbf(bfres(x.z), bfres(x.w));
}
__device__ __forceinline__ void sts_split4(__nv_bfloat16* hi, __nv_bfloat16* lo,
                                           int row, int v, int pad, float4 x) {
    uint2 h, l; split4(x, h, l);
    *(uint2*)(hi + row*pad + v*4) = h;
    *(uint2*)(lo + row*pad + v*4) = l;
}

// ---------------------------------------------------------------------------
// Projection GEMM: C[m,n] = sum_k A[m,k]*W[n,k] + bias[n]  (fp32 in/out)
// 128x128 block, BK=64, 512 threads (16 warps 4m x 4n, warp tile 32x32).
// Double-buffered smem + register prefetch pipeline.
// ---------------------------------------------------------------------------
#define PPAD 72
#define PSLAB (128*PPAD)           // elems per slab
#define PSTAGE (4*PSLAB)           // elems per stage (Ah, Al, Wh, Wl)
#define PROJ_SMEM (2*PSTAGE*2)     // bytes = 147456

__device__ __forceinline__ void proj_mma_kk(uint32_t stage_u, int kk, int wm, int wn,
                                            int lane, float acc[2][4][4])
{
    uint32_t ah[2][4], al[2][4];
    #pragma unroll
    for (int mi = 0; mi < 2; mi++) {
        const int r   = wm*32 + mi*16 + (lane & 15);
        const int col = kk*16 + ((lane & 16) ? 8 : 0);
        ldsm4(ah[mi], stage_u + 2*(0*PSLAB + r*PPAD + col));
        ldsm4(al[mi], stage_u + 2*(1*PSLAB + r*PPAD + col));
    }
    #pragma unroll
    for (int jp = 0; jp < 2; jp++) {
        const int p   = lane >> 3;
        const int r   = wn*32 + jp*16 + ((p >= 2) ? 8 : 0) + (lane & 7);
        const int col = kk*16 + ((p & 1) ? 8 : 0);
        uint32_t th[4], tl[4];
        ldsm4(th, stage_u + 2*(2*PSLAB + r*PPAD + col));
        ldsm4(tl, stage_u + 2*(3*PSLAB + r*PPAD + col));
        #pragma unroll
        for (int mi = 0; mi < 2; mi++) {
            mma16816(acc[mi][2*jp],   ah[mi], th);
            mma16816(acc[mi][2*jp],   ah[mi], tl);
            mma16816(acc[mi][2*jp],   al[mi], th);
            mma16816(acc[mi][2*jp+1], ah[mi], th+2);
            mma16816(acc[mi][2*jp+1], ah[mi], tl+2);
            mma16816(acc[mi][2*jp+1], al[mi], th+2);
        }
    }
}

template<int MODE>   // 0: row-major out; 1: remap to [bh][s][dk]
__device__ __forceinline__ void proj_gemm(const float* __restrict__ A,
                                          const float* __restrict__ W,
                                          const float* __restrict__ bias,
                                          float* __restrict__ C)
{
    extern __shared__ __nv_bfloat16 sm[];
    const uint32_t sb = smem_u32(sm);
    const int tid  = threadIdx.x;
    const int lane = tid & 31;
    const int wid  = tid >> 5;
    const int wm   = wid & 3;
    const int wn   = wid >> 2;
    const int m0 = blockIdx.y * 128;
    const int n0 = blockIdx.x * 128;
    const int lrow = tid >> 4;     // 0..31 (row base; +it*32)
    const int lv   = tid & 15;     // float4 index in row

    float acc[2][4][4];
    #pragma unroll
    for (int mi = 0; mi < 2; mi++)
        #pragma unroll
        for (int nj = 0; nj < 4; nj++)
            #pragma unroll
            for (int e = 0; e < 4; e++) acc[mi][nj][e] = 0.0f;

    float4 pa[4], pw[4];
    // ---- prologue: chunk 0 into stage 0 ----
    #pragma unroll
    for (int it = 0; it < 4; it++)
        pa[it] = *((const float4*)(A + (size_t)(m0 + lrow + it*32)*D_) + lv);
    #pragma unroll
    for (int it = 0; it < 4; it++)
        pw[it] = *((const float4*)(W + (size_t)(n0 + lrow + it*32)*D_) + lv);
    #pragma unroll
    for (int it = 0; it < 4; it++)
        sts_split4(sm + 0*PSLAB, sm + 1*PSLAB, lrow + it*32, lv, PPAD, pa[it]);
    #pragma unroll
    for (int it = 0; it < 4; it++)
        sts_split4(sm + 2*PSLAB, sm + 3*PSLAB, lrow + it*32, lv, PPAD, pw[it]);
    __syncthreads();

    for (int c = 0; c < 16; c++) {
        const int cur = c & 1;
        const int nxt = cur ^ 1;
        const uint32_t scur_u = sb + 2*(cur*PSTAGE);
        __nv_bfloat16* snx = sm + nxt*PSTAGE;
        const int k1 = (c + 1) * 64;

        if (c < 15) {
            #pragma unroll
            for (int it = 0; it < 4; it++)
                pa[it] = *((const float4*)(A + (size_t)(m0 + lrow + it*32)*D_ + k1) + lv);
        }
        proj_mma_kk(scur_u, 0, wm, wn, lane, acc);
        proj_mma_kk(scur_u, 1, wm, wn, lane, acc);
        if (c < 15) {
            #pragma unroll
            for (int it = 0; it < 4; it++)
                sts_split4(snx + 0*PSLAB, snx + 1*PSLAB, lrow + it*32, lv, PPAD, pa[it]);
            #pragma unroll
            for (int it = 0; it < 4; it++)
                pw[it] = *((const float4*)(W + (size_t)(n0 + lrow + it*32)*D_ + k1) + lv);
        }
        proj_mma_kk(scur_u, 2, wm, wn, lane, acc);
        proj_mma_kk(scur_u, 3, wm, wn, lane, acc);
        if (c < 15) {
            #pragma unroll
            for (int it = 0; it < 4; it++)
                sts_split4(snx + 2*PSLAB, snx + 3*PSLAB, lrow + it*32, lv, PPAD, pw[it]);
        }
        __syncthreads();
    }

    // ---- epilogue ----
    const int g  = lane >> 2;
    const int cc = lane & 3;
    #pragma unroll
    for (int mi = 0; mi < 2; mi++) {
        const int ra = m0 + wm*32 + mi*16 + g;
        const int rb = ra + 8;
        #pragma unroll
        for (int nj = 0; nj < 4; nj++) {
            const int col = n0 + wn*32 + nj*8 + cc*2;
            const float b0 = bias[col], b1 = bias[col+1];
            const float v00 = acc[mi][nj][0] + b0, v01 = acc[mi][nj][1] + b1;
            const float v10 = acc[mi][nj][2] + b0, v11 = acc[mi][nj][3] + b1;
            if (MODE == 1) {
                const int h = col >> 6, dk = col & 63;
                const int ba = ra >> 11, sa = ra & (S_-1);
                const int bb = rb >> 11, sb2 = rb & (S_-1);
                *(float2*)&C[(((size_t)ba*H_ + h)*S_ + sa)*DK_ + dk] = make_float2(v00, v01);
                *(float2*)&C[(((size_t)bb*H_ + h)*S_ + sb2)*DK_ + dk] = make_float2(v10, v11);
            } else {
                *(float2*)&C[(size_t)ra*D_ + col] = make_float2(v00, v01);
                *(float2*)&C[(size_t)rb*D_ + col] = make_float2(v10, v11);
            }
        }
    }
}

__global__ void __launch_bounds__(512, 1)
qkv_mma_kernel(const float* __restrict__ q, const float* __restrict__ k,
               const float* __restrict__ v,
               const float* __restrict__ Wq, const float* __restrict__ bq,
               const float* __restrict__ Wk, const float* __restrict__ bk,
               const float* __restrict__ Wv, const float* __restrict__ bv)
{
    const int z = blockIdx.z;
    if (z == 0)      proj_gemm<1>(q, Wq, bq, g_Qh);
    else if (z == 1) proj_gemm<1>(k, Wk, bk, g_Kh);
    else             proj_gemm<1>(v, Wv, bv, g_Vh);
}

__global__ void __launch_bounds__(512, 1)
out_mma_kernel(const float* __restrict__ Wo, const float* __restrict__ bo,
               float* __restrict__ out)
{
    proj_gemm<0>(g_att, Wo, bo, out);
}

// ---------------------------------------------------------------------------
// Flash attention on mma.sync. 256 threads (8 warps x m16 = 128 q rows),
// 64-key tiles, K and V double-buffered with register prefetch.
// Mask: mask[b, q] masks QUERY rows (broadcast over keys).
// ---------------------------------------------------------------------------
#define APAD 72
#define ASLAB (64*APAD)             // 4608 elems per KV slab
// slabs: 0=K0h 1=K0l 2=K1h 3=K1l 4=V0h 5=V0l 6=V1h 7=V1l
#define ATT_SMEM (8*ASLAB*2)        // 73728 B; Q phase (2*128*APAD*2=36864) fits

__global__ void __launch_bounds__(256, 1)
attn_mma_kernel(const int* __restrict__ mask)
{
    extern __shared__ __nv_bfloat16 sm[];
    const uint32_t sb = smem_u32(sm);
    const int tid  = threadIdx.x;
    const int lane = tid & 31;
    const int wid  = tid >> 5;
    const int g    = lane >> 2;
    const int cc   = lane & 3;
    const int lrow = tid >> 4;      // 0..15
    const int lv   = tid & 15;

    const int bh = blockIdx.y;
    const int b  = bh >> 4;
    const int h  = bh & 15;
    const int q0 = blockIdx.x * 128;

    const float* Qp = g_Qh + (size_t)bh*S_*DK_;
    const float* Kp = g_Kh + (size_t)bh*S_*DK_;
    const float* Vp = g_Vh + (size_t)bh*S_*DK_;
    const int* mp = mask + b*S_;

    // ---- Q tile (128x64 fp32 -> hi/lo slabs at 0 / 128*APAD), extract frags ----
    #pragma unroll
    for (int it = 0; it < 8; it++) {
        const int row = lrow + it*16;
        float4 x = *((const float4*)(Qp + (size_t)(q0+row)*DK_) + lv);
        sts_split4(sm, sm + 128*APAD, row, lv, APAD, x);
    }
    __syncthreads();

    uint32_t qh[4][4], ql[4][4];
    #pragma unroll
    for (int kk = 0; kk < 4; kk++) {
        const int r   = wid*16 + (lane & 15);
        const int col = kk*16 + ((lane & 16) ? 8 : 0);
        ldsm4(qh[kk], sb + 2*(0        + r*APAD + col));
        ldsm4(ql[kk], sb + 2*(128*APAD + r*APAD + col));
    }
    __syncthreads();   // everyone done reading Q region before KV overwrite

    const int qr0 = q0 + wid*16 + g;
    const int qr1 = qr0 + 8;
    const bool msk0 = (mp[qr0] == 0);
    const bool msk1 = (mp[qr1] == 0);

    float mr0 = -1e30f, mr1 = -1e30f, lr0 = 0.0f, lr1 = 0.0f;
    float oacc[8][4];
    #pragma unroll
    for (int nj = 0; nj < 8; nj++)
        #pragma unroll
        for (int e = 0; e < 4; e++) oacc[nj][e] = 0.0f;

    float4 pk[4], pv[4];
    // ---- prologue: KV tile 0 into buffers 0 ----
    #pragma unroll
    for (int it = 0; it < 4; it++)
        pk[it] = *((const float4*)(Kp + (size_t)(lrow + it*16)*DK_) + lv);
    #pragma unroll
    for (int it = 0; it < 4; it++)
        pv[it] = *((const float4*)(Vp + (size_t)(lrow + it*16)*DK_) + lv);
    #pragma unroll
    for (int it = 0; it < 4; it++)
        sts_split4(sm + 0*ASLAB, sm + 1*ASLAB, lrow + it*16, lv, APAD, pk[it]);
    #pragma unroll
    for (int it = 0; it < 4; it++)
        sts_split4(sm + 4*ASLAB, sm + 5*ASLAB, lrow + it*16, lv, APAD, pv[it]);
    __syncthreads();

    for (int t = 0; t < 32; t++) {
        const int cur = t & 1;
        const int nxt = cur ^ 1;
        const bool pf = (t + 1 < 32);
        const int kt1 = (t + 1) * 64;
        const uint32_t kcur_u = sb + 2*((2*cur)*ASLAB);
        const uint32_t vcur_u = sb + 2*((4 + 2*cur)*ASLAB);

        // prefetch K(t+1)
        if (pf) {
            #pragma unroll
            for (int it = 0; it < 4; it++)
                pk[it] = *((const float4*)(Kp + (size_t)(kt1 + lrow + it*16)*DK_) + lv);
        }

        // ---- S = Q K^T on K[cur] ----
        float sacc[8][4];
        #pragma unroll
        for (int nj = 0; nj < 8; nj++)
            #pragma unroll
            for (int e = 0; e < 4; e++) sacc[nj][e] = 0.0f;

        #pragma unroll
        for (int kk = 0; kk < 4; kk++) {
            #pragma unroll
            for (int jp = 0; jp < 4; jp++) {
                const int p   = lane >> 3;
                const int r   = jp*16 + ((p >= 2) ? 8 : 0) + (lane & 7);
                const int col = kk*16 + ((p & 1) ? 8 : 0);
                uint32_t th[4], tl[4];
                ldsm4(th, kcur_u + 2*(0*ASLAB + r*APAD + col));
                ldsm4(tl, kcur_u + 2*(1*ASLAB + r*APAD + col));
                mma16816(sacc[2*jp],   qh[kk], th);
                mma16816(sacc[2*jp],   qh[kk], tl);
                mma16816(sacc[2*jp],   ql[kk], th);
                mma16816(sacc[2*jp+1], qh[kk], th+2);
                mma16816(sacc[2*jp+1], qh[kk], tl+2);
                mma16816(sacc[2*jp+1], ql[kk], th+2);
            }
        }

        // store prefetched K, prefetch V(t+1)
        if (pf) {
            #pragma unroll
            for (int it = 0; it < 4; it++)
                sts_split4(sm + (2*nxt)*ASLAB, sm + (2*nxt+1)*ASLAB,
                           lrow + it*16, lv, APAD, pk[it]);
            #pragma unroll
            for (int it = 0; it < 4; it++)
                pv[it] = *((const float4*)(Vp + (size_t)(kt1 + lrow + it*16)*DK_) + lv);
        }

        // ---- mask + online softmax ----
        if (msk0) {
            #pragma unroll
            for (int nj = 0; nj < 8; nj++) { sacc[nj][0] = NEGINF; sacc[nj][1] = NEGINF; }
        }
        if (msk1) {
            #pragma unroll
            for (int nj = 0; nj < 8; nj++) { sacc[nj][2] = NEGINF; sacc[nj][3] = NEGINF; }
        }

        float mx0 = -1e30f, mx1 = -1e30f;
        #pragma unroll
        for (int nj = 0; nj < 8; nj++) {
            mx0 = fmaxf(mx0, fmaxf(sacc[nj][0], sacc[nj][1]));
            mx1 = fmaxf(mx1, fmaxf(sacc[nj][2], sacc[nj][3]));
        }
        mx0 = fmaxf(mx0, __shfl_xor_sync(0xffffffffu, mx0, 1));
        mx0 = fmaxf(mx0, __shfl_xor_sync(0xffffffffu, mx0, 2));
        mx1 = fmaxf(mx1, __shfl_xor_sync(0xffffffffu, mx1, 1));
        mx1 = fmaxf(mx1, __shfl_xor_sync(0xffffffffu, mx1, 2));

        const float mn0 = fmaxf(mr0, mx0);
        const float mn1 = fmaxf(mr1, mx1);
        const float al0 = __expf(mr0 - mn0);
        const float al1 = __expf(mr1 - mn1);
        mr0 = mn0; mr1 = mn1;

        float rs0 = 0.0f, rs1 = 0.0f;
        #pragma unroll
        for (int nj = 0; nj < 8; nj++) {
            const float p0 = __expf(sacc[nj][0] - mn0);
            const float p1 = __expf(sacc[nj][1] - mn0);
            const float p2 = __expf(sacc[nj][2] - mn1);
            const float p3 = __expf(sacc[nj][3] - mn1);
            sacc[nj][0] = p0; sacc[nj][1] = p1; sacc[nj][2] = p2; sacc[nj][3] = p3;
            rs0 += p0 + p1; rs1 += p2 + p3;
        }
        rs0 += __shfl_xor_sync(0xffffffffu, rs0, 1);
        rs0 += __shfl_xor_sync(0xffffffffu, rs0, 2);
        rs1 += __shfl_xor_sync(0xffffffffu, rs1, 1);
        rs1 += __shfl_xor_sync(0xffffffffu, rs1, 2);
        lr0 = lr0*al0 + rs0;
        lr1 = lr1*al1 + rs1;

        #pragma unroll
        for (int nj = 0; nj < 8; nj++) {
            oacc[nj][0] *= al0; oacc[nj][1] *= al0;
            oacc[nj][2] *= al1; oacc[nj][3] *= al1;
        }

        // ---- O += P V on V[cur] ----
        #pragma unroll
        for (int t4 = 0; t4 < 4; t4++) {
            const float p00 = sacc[2*t4][0],   p01 = sacc[2*t4][1];
            const float p02 = sacc[2*t4][2],   p03 = sacc[2*t4][3];
            const float p10 = sacc[2*t4+1][0], p11 = sacc[2*t4+1][1];
            const float p12 = sacc[2*t4+1][2], p13 = sacc[2*t4+1][3];
            uint32_t pa[4], pl[4];
            pa[0] = packbf(p00, p01); pa[1] = packbf(p02, p03);
            pa[2] = packbf(p10, p11); pa[3] = packbf(p12, p13);
            pl[0] = packbf(bfres(p00), bfres(p01)); pl[1] = packbf(bfres(p02), bfres(p03));
            pl[2] = packbf(bfres(p10), bfres(p11)); pl[3] = packbf(bfres(p12), bfres(p13));

            #pragma unroll
            for (int jp = 0; jp < 4; jp++) {
                const int p   = lane >> 3;
                const int r   = t4*16 + ((p & 1) ? 8 : 0) + (lane & 7);
                const int col = jp*16 + ((p >= 2) ? 8 : 0);
                uint32_t th[4], tl[4];
                ldsm4_t(th, vcur_u + 2*(0*ASLAB + r*APAD + col));
                ldsm4_t(tl, vcur_u + 2*(1*ASLAB + r*APAD + col));
                mma16816(oacc[2*jp],   pa, th);
                mma16816(oacc[2*jp],   pa, tl);
                mma16816(oacc[2*jp],   pl, th);
                mma16816(oacc[2*jp+1], pa, th+2);
                mma16816(oacc[2*jp+1], pa, tl+2);
                mma16816(oacc[2*jp+1], pl, th+2);
            }
        }

        // store prefetched V
        if (pf) {
            #pragma unroll
            for (int it = 0; it < 4; it++)
                sts_split4(sm + (4 + 2*nxt)*ASLAB, sm + (4 + 2*nxt + 1)*ASLAB,
                           lrow + it*16, lv, APAD, pv[it]);
        }
        __syncthreads();
    }

    // ---- epilogue: att = oacc / l, fp32 concat [b,s,h*64+dk] ----
    const float inv0 = 1.0f / lr0;
    const float inv1 = 1.0f / lr1;
    float* outa = g_att + ((size_t)(b*S_ + qr0))*D_ + h*DK_;
    float* outb = g_att + ((size_t)(b*S_ + qr1))*D_ + h*DK_;
    #pragma unroll
    for (int nj = 0; nj < 8; nj++) {
        const int dk = nj*8 + cc*2;
        *(float2*)&outa[dk] = make_float2(oacc[nj][0]*inv0, oacc[nj][1]*inv0);
        *(float2*)&outb[dk] = make_float2(oacc[nj][2]*inv1, oacc[nj][3]*inv1);
    }
}

// ---------------------------------------------------------------------------
extern "C" void kernel_launch(void* const* d_in, const int* in_sizes, int n_in,
                              void* d_out, int out_size)
{
    const float* q    = (const float*)d_in[0];
    const float* k    = (const float*)d_in[1];
    const float* v    = (const float*)d_in[2];
    const int*   mask = (const int*)  d_in[3];
    const float* Wq   = (const float*)d_in[4];
    const float* bq   = (const float*)d_in[5];
    const float* Wk   = (const float*)d_in[6];
    const float* bk   = (const float*)d_in[7];
    const float* Wv   = (const float*)d_in[8];
    const float* bv   = (const float*)d_in[9];
    const float* Wo   = (const float*)d_in[10];
    const float* bo   = (const float*)d_in[11];
    float* out = (float*)d_out;

    static int configured = 0;
    if (!configured) {
        cudaFuncSetAttribute(qkv_mma_kernel, cudaFuncAttributeMaxDynamicSharedMemorySize, PROJ_SMEM);
        cudaFuncSetAttribute(out_mma_kernel, cudaFuncAttributeMaxDynamicSharedMemorySize, PROJ_SMEM);
        cudaFuncSetAttribute(attn_mma_kernel, cudaFuncAttributeMaxDynamicSharedMemorySize, ATT_SMEM);
        configured = 1;
    }

    // 1. QKV projections
    qkv_mma_kernel<<<dim3(D_/128, M_/128, 3), 512, PROJ_SMEM>>>(
        q, k, v, Wq, bq, Wk, bk, Wv, bv);

    // 2. Attention
    attn_mma_kernel<<<dim3(S_/128, B_*H_), 256, ATT_SMEM>>>(mask);

    // 3. Output projection
    out_mma_kernel<<<dim3(D_/128, M_/128), 512, PROJ_SMEM>>>(Wo, bo, out);
}

// round 8
// speedup vs baseline: 3.2463x; 1.0410x over previous
#include <cuda_runtime.h>
#include <cuda_bf16.h>
#include <cstdint>
#include <math.h>

#define B_ 2
#define S_ 2048
#define D_ 1024
#define H_ 16
#define DK_ 64
#define M_ (B_*S_)
#define NEGINF (-1000000000.0f)

// ---------------------------------------------------------------------------
// Scratch: 64 MiB total (proven-safe budget), all bf16 hi/lo pairs.
// ---------------------------------------------------------------------------
__device__ __nv_bfloat16 g_Qh_hi[M_*D_], g_Qh_lo[M_*D_];   // [bh][s][dk] 8 MiB each
__device__ __nv_bfloat16 g_Kh_hi[M_*D_], g_Kh_lo[M_*D_];
__device__ __nv_bfloat16 g_Vh_hi[M_*D_], g_Vh_lo[M_*D_];
__device__ __nv_bfloat16 g_att_hi[M_*D_], g_att_lo[M_*D_]; // [m][d]

// ---------------------------------------------------------------------------
// PTX helpers (base sm_100-legal: ldmatrix + mma.sync)
// ---------------------------------------------------------------------------
__device__ __forceinline__ uint32_t smem_u32(const void* p) {
    uint32_t a;
    asm("{ .reg .u64 t; cvta.to.shared.u64 t, %1; cvt.u32.u64 %0, t; }" : "=r"(a) : "l"(p));
    return a;
}
__device__ __forceinline__ void ldsm4(uint32_t* r, uint32_t addr) {
    asm volatile("ldmatrix.sync.aligned.m8n8.x4.shared.b16 {%0,%1,%2,%3}, [%4];"
        : "=r"(r[0]), "=r"(r[1]), "=r"(r[2]), "=r"(r[3]) : "r"(addr));
}
__device__ __forceinline__ void ldsm4_t(uint32_t* r, uint32_t addr) {
    asm volatile("ldmatrix.sync.aligned.m8n8.x4.trans.shared.b16 {%0,%1,%2,%3}, [%4];"
        : "=r"(r[0]), "=r"(r[1]), "=r"(r[2]), "=r"(r[3]) : "r"(addr));
}
__device__ __forceinline__ void mma16816(float* d, const uint32_t* a, const uint32_t* b) {
    asm volatile(
        "mma.sync.aligned.m16n8k16.row.col.f32.bf16.bf16.f32 "
        "{%0,%1,%2,%3}, {%4,%5,%6,%7}, {%8,%9}, {%0,%1,%2,%3};"
        : "+f"(d[0]), "+f"(d[1]), "+f"(d[2]), "+f"(d[3])
        : "r"(a[0]), "r"(a[1]), "r"(a[2]), "r"(a[3]), "r"(b[0]), "r"(b[1]));
}
__device__ __forceinline__ uint32_t packbf(float lo, float hi) {
    uint32_t r;
    asm("cvt.rn.bf16x2.f32 %0, %1, %2;" : "=r"(r) : "f"(hi), "f"(lo));
    return r;
}
__device__ __forceinline__ float bfres(float x) {
    return x - __bfloat162float(__float2bfloat16(x));
}
__device__ __forceinline__ void split4(float4 x, uint2& h, uint2& l) {
    h.x = packbf(x.x, x.y);  h.y = packbf(x.z, x.w);
    l.x = packbf(bfres(x.x), bfres(x.y));
    l.y = packbf(bfres(x.z), bfres(x.w));
}
__device__ __forceinline__ void sts_split4(__nv_bfloat16* hi, __nv_bfloat16* lo,
                                           int row, int v, int pad, float4 x) {
    uint2 h, l; split4(x, h, l);
    *(uint2*)(hi + row*pad + v*4) = h;
    *(uint2*)(lo + row*pad + v*4) = l;
}

// ---------------------------------------------------------------------------
// Projection GEMM: C[m,n] = sum_k A[m,k]*W[n,k] + bias[n]
// 128x128 block, BK=64, 512 threads (16 warps 4m x 4n, warp tile 32x32).
// Double-buffered smem + register prefetch pipeline.
// ABF16=0: A fp32, split in-kernel. ABF16=1: A given as bf16 hi/lo arrays.
// MODE=0: fp32 row-major out.  MODE=1: bf16 hi/lo remapped to [bh][s][dk].
// ---------------------------------------------------------------------------
#define PPAD 72
#define PSLAB (128*PPAD)
#define PSTAGE (4*PSLAB)
#define PROJ_SMEM (2*PSTAGE*2)     // 147456 B

__device__ __forceinline__ void proj_mma_kk(uint32_t stage_u, int kk, int wm, int wn,
                                            int lane, float acc[2][4][4])
{
    uint32_t ah[2][4], al[2][4];
    #pragma unroll
    for (int mi = 0; mi < 2; mi++) {
        const int r   = wm*32 + mi*16 + (lane & 15);
        const int col = kk*16 + ((lane & 16) ? 8 : 0);
        ldsm4(ah[mi], stage_u + 2*(0*PSLAB + r*PPAD + col));
        ldsm4(al[mi], stage_u + 2*(1*PSLAB + r*PPAD + col));
    }
    #pragma unroll
    for (int jp = 0; jp < 2; jp++) {
        const int p   = lane >> 3;
        const int r   = wn*32 + jp*16 + ((p >= 2) ? 8 : 0) + (lane & 7);
        const int col = kk*16 + ((p & 1) ? 8 : 0);
        uint32_t th[4], tl[4];
        ldsm4(th, stage_u + 2*(2*PSLAB + r*PPAD + col));
        ldsm4(tl, stage_u + 2*(3*PSLAB + r*PPAD + col));
        #pragma unroll
        for (int mi = 0; mi < 2; mi++) {
            mma16816(acc[mi][2*jp],   ah[mi], th);
            mma16816(acc[mi][2*jp],   ah[mi], tl);
            mma16816(acc[mi][2*jp],   al[mi], th);
            mma16816(acc[mi][2*jp+1], ah[mi], th+2);
            mma16816(acc[mi][2*jp+1], ah[mi], tl+2);
            mma16816(acc[mi][2*jp+1], al[mi], th+2);
        }
    }
}

template<int MODE, int ABF16>
__device__ __forceinline__ void proj_gemm(const float* __restrict__ Af,
                                          const __nv_bfloat16* __restrict__ Ahi,
                                          const __nv_bfloat16* __restrict__ Alo,
                                          const float* __restrict__ W,
                                          const float* __restrict__ bias,
                                          float* __restrict__ Cf,
                                          __nv_bfloat16* __restrict__ Chi,
                                          __nv_bfloat16* __restrict__ Clo)
{
    extern __shared__ __nv_bfloat16 sm[];
    const uint32_t sb = smem_u32(sm);
    const int tid  = threadIdx.x;
    const int lane = tid & 31;
    const int wid  = tid >> 5;
    const int wm   = wid & 3;
    const int wn   = wid >> 2;
    const int m0 = blockIdx.y * 128;
    const int n0 = blockIdx.x * 128;

    float acc[2][4][4];
    #pragma unroll
    for (int mi = 0; mi < 2; mi++)
        #pragma unroll
        for (int nj = 0; nj < 4; nj++)
            #pragma unroll
            for (int e = 0; e < 4; e++) acc[mi][nj][e] = 0.0f;

    float4 paf[4], pw[4];
    uint4 pab[2][2];   // [hi/lo][it] for ABF16 path

    // ---- prologue: chunk 0 -> stage 0 ----
    if (ABF16) {
        #pragma unroll
        for (int it = 0; it < 2; it++) {
            const int idx = tid + it*512;          // 0..1023
            const int row = idx >> 3, v = idx & 7;
            pab[0][it] = *((const uint4*)(Ahi + (size_t)(m0+row)*D_) + v);
            pab[1][it] = *((const uint4*)(Alo + (size_t)(m0+row)*D_) + v);
            *(uint4*)(sm + 0*PSLAB + row*PPAD + v*8) = pab[0][it];
            *(uint4*)(sm + 1*PSLAB + row*PPAD + v*8) = pab[1][it];
        }
    } else {
        #pragma unroll
        for (int it = 0; it < 4; it++) {
            const int idx = tid + it*512;          // 0..2047
            const int row = idx >> 4, v = idx & 15;
            paf[it] = *((const float4*)(Af + (size_t)(m0+row)*D_) + v);
            sts_split4(sm + 0*PSLAB, sm + 1*PSLAB, row, v, PPAD, paf[it]);
        }
    }
    #pragma unroll
    for (int it = 0; it < 4; it++) {
        const int idx = tid + it*512;
        const int row = idx >> 4, v = idx & 15;
        pw[it] = *((const float4*)(W + (size_t)(n0+row)*D_) + v);
        sts_split4(sm + 2*PSLAB, sm + 3*PSLAB, row, v, PPAD, pw[it]);
    }
    __syncthreads();

    for (int c = 0; c < 16; c++) {
        const int cur = c & 1;
        const int nxt = cur ^ 1;
        const uint32_t scur_u = sb + 2*(cur*PSTAGE);
        __nv_bfloat16* snx = sm + nxt*PSTAGE;
        const int k1 = (c + 1) * 64;
        const bool pf = (c < 15);

        // prefetch A(c+1)
        if (pf) {
            if (ABF16) {
                #pragma unroll
                for (int it = 0; it < 2; it++) {
                    const int idx = tid + it*512;
                    const int row = idx >> 3, v = idx & 7;
                    pab[0][it] = *((const uint4*)(Ahi + (size_t)(m0+row)*D_ + k1) + v);
                    pab[1][it] = *((const uint4*)(Alo + (size_t)(m0+row)*D_ + k1) + v);
                }
            } else {
                #pragma unroll
                for (int it = 0; it < 4; it++) {
                    const int idx = tid + it*512;
                    const int row = idx >> 4, v = idx & 15;
                    paf[it] = *((const float4*)(Af + (size_t)(m0+row)*D_ + k1) + v);
                }
            }
        }
        proj_mma_kk(scur_u, 0, wm, wn, lane, acc);
        proj_mma_kk(scur_u, 1, wm, wn, lane, acc);
        if (pf) {
            if (ABF16) {
                #pragma unroll
                for (int it = 0; it < 2; it++) {
                    const int idx = tid + it*512;
                    const int row = idx >> 3, v = idx & 7;
                    *(uint4*)(snx + 0*PSLAB + row*PPAD + v*8) = pab[0][it];
                    *(uint4*)(snx + 1*PSLAB + row*PPAD + v*8) = pab[1][it];
                }
            } else {
                #pragma unroll
                for (int it = 0; it < 4; it++) {
                    const int idx = tid + it*512;
                    const int row = idx >> 4, v = idx & 15;
                    sts_split4(snx + 0*PSLAB, snx + 1*PSLAB, row, v, PPAD, paf[it]);
                }
            }
            #pragma unroll
            for (int it = 0; it < 4; it++) {
                const int idx = tid + it*512;
                const int row = idx >> 4, v = idx & 15;
                pw[it] = *((const float4*)(W + (size_t)(n0+row)*D_ + k1) + v);
            }
        }
        proj_mma_kk(scur_u, 2, wm, wn, lane, acc);
        proj_mma_kk(scur_u, 3, wm, wn, lane, acc);
        if (pf) {
            #pragma unroll
            for (int it = 0; it < 4; it++) {
                const int idx = tid + it*512;
                const int row = idx >> 4, v = idx & 15;
                sts_split4(snx + 2*PSLAB, snx + 3*PSLAB, row, v, PPAD, pw[it]);
            }
        }
        __syncthreads();
    }

    // ---- epilogue ----
    const int g  = lane >> 2;
    const int cc = lane & 3;
    #pragma unroll
    for (int mi = 0; mi < 2; mi++) {
        const int ra = m0 + wm*32 + mi*16 + g;
        const int rb = ra + 8;
        #pragma unroll
        for (int nj = 0; nj < 4; nj++) {
            const int col = n0 + wn*32 + nj*8 + cc*2;
            const float b0 = bias[col], b1 = bias[col+1];
            const float v00 = acc[mi][nj][0] + b0, v01 = acc[mi][nj][1] + b1;
            const float v10 = acc[mi][nj][2] + b0, v11 = acc[mi][nj][3] + b1;
            if (MODE == 1) {
                const int h = col >> 6, dk = col & 63;
                const int ba = ra >> 11, sa = ra & (S_-1);
                const int bb = rb >> 11, sb2 = rb & (S_-1);
                const size_t ia = (((size_t)ba*H_ + h)*S_ + sa)*DK_ + dk;
                const size_t ib = (((size_t)bb*H_ + h)*S_ + sb2)*DK_ + dk;
                *(uint32_t*)&Chi[ia] = packbf(v00, v01);
                *(uint32_t*)&Clo[ia] = packbf(bfres(v00), bfres(v01));
                *(uint32_t*)&Chi[ib] = packbf(v10, v11);
                *(uint32_t*)&Clo[ib] = packbf(bfres(v10), bfres(v11));
            } else {
                *(float2*)&Cf[(size_t)ra*D_ + col] = make_float2(v00, v01);
                *(float2*)&Cf[(size_t)rb*D_ + col] = make_float2(v10, v11);
            }
        }
    }
}

__global__ void __launch_bounds__(512, 1)
qkv_mma_kernel(const float* __restrict__ q, const float* __restrict__ k,
               const float* __restrict__ v,
               const float* __restrict__ Wq, const float* __restrict__ bq,
               const float* __restrict__ Wk, const float* __restrict__ bk,
               const float* __restrict__ Wv, const float* __restrict__ bv)
{
    const int z = blockIdx.z;
    if (z == 0)      proj_gemm<1,0>(q, nullptr, nullptr, Wq, bq, nullptr, g_Qh_hi, g_Qh_lo);
    else if (z == 1) proj_gemm<1,0>(k, nullptr, nullptr, Wk, bk, nullptr, g_Kh_hi, g_Kh_lo);
    else             proj_gemm<1,0>(v, nullptr, nullptr, Wv, bv, nullptr, g_Vh_hi, g_Vh_lo);
}

__global__ void __launch_bounds__(512, 1)
out_mma_kernel(const float* __restrict__ Wo, const float* __restrict__ bo,
               float* __restrict__ out)
{
    proj_gemm<0,1>(nullptr, g_att_hi, g_att_lo, Wo, bo, out, nullptr, nullptr);
}

// ---------------------------------------------------------------------------
// Flash attention on mma.sync. 512 threads (16 warps x m16 = 256 q rows),
// 64-key tiles, K/V double-buffered with register prefetch, bf16 hi/lo I/O.
// Mask: mask[b, q] masks QUERY rows (broadcast over keys).
// ---------------------------------------------------------------------------
#define APAD 72
#define AQSLAB (256*APAD)
#define ASLAB (64*APAD)
// KV slabs: 0=K0h 1=K0l 2=K1h 3=K1l 4=V0h 5=V0l 6=V1h 7=V1l  (reuses Q region)
#define ATT_SMEM (2*AQSLAB*2)       // 73728 B == 8*ASLAB*2

__global__ void __launch_bounds__(512, 1)
attn_mma_kernel(const int* __restrict__ mask)
{
    extern __shared__ __nv_bfloat16 sm[];
    const uint32_t sb = smem_u32(sm);
    const int tid  = threadIdx.x;
    const int lane = tid & 31;
    const int wid  = tid >> 5;       // 0..15
    const int g    = lane >> 2;
    const int cc   = lane & 3;
    const int krow = tid >> 3;       // 0..63 (one uint4 per slab per thread)
    const int kv   = tid & 7;

    const int bh = blockIdx.y;
    const int b  = bh >> 4;
    const int h  = bh & 15;
    const int q0 = blockIdx.x * 256;

    const __nv_bfloat16* Qhi = g_Qh_hi + (size_t)bh*S_*DK_;
    const __nv_bfloat16* Qlo = g_Qh_lo + (size_t)bh*S_*DK_;
    const __nv_bfloat16* Khi = g_Kh_hi + (size_t)bh*S_*DK_;
    const __nv_bfloat16* Klo = g_Kh_lo + (size_t)bh*S_*DK_;
    const __nv_bfloat16* Vhi = g_Vh_hi + (size_t)bh*S_*DK_;
    const __nv_bfloat16* Vlo = g_Vh_lo + (size_t)bh*S_*DK_;
    const int* mp = mask + b*S_;

    // ---- Q tile (256x64 hi/lo) -> smem, extract frags ----
    #pragma unroll
    for (int it = 0; it < 4; it++) {
        const int idx = tid + it*512;            // 0..2047
        const int row = idx >> 3, v = idx & 7;
        *(uint4*)(sm + 0      + row*APAD + v*8) =
            *((const uint4*)(Qhi + (size_t)(q0+row)*DK_) + v);
        *(uint4*)(sm + AQSLAB + row*APAD + v*8) =
            *((const uint4*)(Qlo + (size_t)(q0+row)*DK_) + v);
    }
    __syncthreads();

    uint32_t qh[4][4], ql[4][4];
    #pragma unroll
    for (int kk = 0; kk < 4; kk++) {
        const int r   = wid*16 + (lane & 15);
        const int col = kk*16 + ((lane & 16) ? 8 : 0);
        ldsm4(qh[kk], sb + 2*(0      + r*APAD + col));
        ldsm4(ql[kk], sb + 2*(AQSLAB + r*APAD + col));
    }
    __syncthreads();   // Q region free for KV reuse

    const int qr0 = q0 + wid*16 + g;
    const int qr1 = qr0 + 8;
    const bool msk0 = (mp[qr0] == 0);
    const bool msk1 = (mp[qr1] == 0);

    float mr0 = -1e30f, mr1 = -1e30f, lr0 = 0.0f, lr1 = 0.0f;
    float oacc[8][4];
    #pragma unroll
    for (int nj = 0; nj < 8; nj++)
        #pragma unroll
        for (int e = 0; e < 4; e++) oacc[nj][e] = 0.0f;

    uint4 pk[2], pv[2];
    // ---- prologue: KV tile 0 -> buffers 0 ----
    pk[0] = *((const uint4*)(Khi + (size_t)krow*DK_) + kv);
    pk[1] = *((const uint4*)(Klo + (size_t)krow*DK_) + kv);
    pv[0] = *((const uint4*)(Vhi + (size_t)krow*DK_) + kv);
    pv[1] = *((const uint4*)(Vlo + (size_t)krow*DK_) + kv);
    *(uint4*)(sm + 0*ASLAB + krow*APAD + kv*8) = pk[0];
    *(uint4*)(sm + 1*ASLAB + krow*APAD + kv*8) = pk[1];
    *(uint4*)(sm + 4*ASLAB + krow*APAD + kv*8) = pv[0];
    *(uint4*)(sm + 5*ASLAB + krow*APAD + kv*8) = pv[1];
    __syncthreads();

    for (int t = 0; t < 32; t++) {
        const int cur = t & 1;
        const int nxt = cur ^ 1;
        const bool pf = (t + 1 < 32);
        const size_t off1 = (size_t)((t + 1)*64 + krow) * DK_;
        const uint32_t kcur_u = sb + 2*((2*cur)*ASLAB);
        const uint32_t vcur_u = sb + 2*((4 + 2*cur)*ASLAB);

        if (pf) {
            pk[0] = *((const uint4*)(Khi + off1) + kv);
            pk[1] = *((const uint4*)(Klo + off1) + kv);
        }

        // ---- S = Q K^T ----
        float sacc[8][4];
        #pragma unroll
        for (int nj = 0; nj < 8; nj++)
            #pragma unroll
            for (int e = 0; e < 4; e++) sacc[nj][e] = 0.0f;

        #pragma unroll
        for (int kk = 0; kk < 4; kk++) {
            #pragma unroll
            for (int jp = 0; jp < 4; jp++) {
                const int p   = lane >> 3;
                const int r   = jp*16 + ((p >= 2) ? 8 : 0) + (lane & 7);
                const int col = kk*16 + ((p & 1) ? 8 : 0);
                uint32_t th[4], tl[4];
                ldsm4(th, kcur_u + 2*(0*ASLAB + r*APAD + col));
                ldsm4(tl, kcur_u + 2*(1*ASLAB + r*APAD + col));
                mma16816(sacc[2*jp],   qh[kk], th);
                mma16816(sacc[2*jp],   qh[kk], tl);
                mma16816(sacc[2*jp],   ql[kk], th);
                mma16816(sacc[2*jp+1], qh[kk], th+2);
                mma16816(sacc[2*jp+1], qh[kk], tl+2);
                mma16816(sacc[2*jp+1], ql[kk], th+2);
            }
        }

        if (pf) {
            *(uint4*)(sm + (2*nxt)*ASLAB   + krow*APAD + kv*8) = pk[0];
            *(uint4*)(sm + (2*nxt+1)*ASLAB + krow*APAD + kv*8) = pk[1];
            pv[0] = *((const uint4*)(Vhi + off1) + kv);
            pv[1] = *((const uint4*)(Vlo + off1) + kv);
        }

        // ---- mask + online softmax ----
        if (msk0) {
            #pragma unroll
            for (int nj = 0; nj < 8; nj++) { sacc[nj][0] = NEGINF; sacc[nj][1] = NEGINF; }
        }
        if (msk1) {
            #pragma unroll
            for (int nj = 0; nj < 8; nj++) { sacc[nj][2] = NEGINF; sacc[nj][3] = NEGINF; }
        }

        float mx0 = -1e30f, mx1 = -1e30f;
        #pragma unroll
        for (int nj = 0; nj < 8; nj++) {
            mx0 = fmaxf(mx0, fmaxf(sacc[nj][0], sacc[nj][1]));
            mx1 = fmaxf(mx1, fmaxf(sacc[nj][2], sacc[nj][3]));
        }
        mx0 = fmaxf(mx0, __shfl_xor_sync(0xffffffffu, mx0, 1));
        mx0 = fmaxf(mx0, __shfl_xor_sync(0xffffffffu, mx0, 2));
        mx1 = fmaxf(mx1, __shfl_xor_sync(0xffffffffu, mx1, 1));
        mx1 = fmaxf(mx1, __shfl_xor_sync(0xffffffffu, mx1, 2));

        const float mn0 = fmaxf(mr0, mx0);
        const float mn1 = fmaxf(mr1, mx1);
        const float al0 = __expf(mr0 - mn0);
        const float al1 = __expf(mr1 - mn1);
        mr0 = mn0; mr1 = mn1;

        float rs0 = 0.0f, rs1 = 0.0f;
        #pragma unroll
        for (int nj = 0; nj < 8; nj++) {
            const float p0 = __expf(sacc[nj][0] - mn0);
            const float p1 = __expf(sacc[nj][1] - mn0);
            const float p2 = __expf(sacc[nj][2] - mn1);
            const float p3 = __expf(sacc[nj][3] - mn1);
            sacc[nj][0] = p0; sacc[nj][1] = p1; sacc[nj][2] = p2; sacc[nj][3] = p3;
            rs0 += p0 + p1; rs1 += p2 + p3;
        }
        rs0 += __shfl_xor_sync(0xffffffffu, rs0, 1);
        rs0 += __shfl_xor_sync(0xffffffffu, rs0, 2);
        rs1 += __shfl_xor_sync(0xffffffffu, rs1, 1);
        rs1 += __shfl_xor_sync(0xffffffffu, rs1, 2);
        lr0 = lr0*al0 + rs0;
        lr1 = lr1*al1 + rs1;

        #pragma unroll
        for (int nj = 0; nj < 8; nj++) {
            oacc[nj][0] *= al0; oacc[nj][1] *= al0;
            oacc[nj][2] *= al1; oacc[nj][3] *= al1;
        }

        // ---- O += P V ----
        #pragma unroll
        for (int t4 = 0; t4 < 4; t4++) {
            const float p00 = sacc[2*t4][0],   p01 = sacc[2*t4][1];
            const float p02 = sacc[2*t4][2],   p03 = sacc[2*t4][3];
            const float p10 = sacc[2*t4+1][0], p11 = sacc[2*t4+1][1];
            const float p12 = sacc[2*t4+1][2], p13 = sacc[2*t4+1][3];
            uint32_t pa[4], pl[4];
            pa[0] = packbf(p00, p01); pa[1] = packbf(p02, p03);
            pa[2] = packbf(p10, p11); pa[3] = packbf(p12, p13);
            pl[0] = packbf(bfres(p00), bfres(p01)); pl[1] = packbf(bfres(p02), bfres(p03));
            pl[2] = packbf(bfres(p10), bfres(p11)); pl[3] = packbf(bfres(p12), bfres(p13));

            #pragma unroll
            for (int jp = 0; jp < 4; jp++) {
                const int p   = lane >> 3;
                const int r   = t4*16 + ((p & 1) ? 8 : 0) + (lane & 7);
                const int col = jp*16 + ((p >= 2) ? 8 : 0);
                uint32_t th[4], tl[4];
                ldsm4_t(th, vcur_u + 2*(0*ASLAB + r*APAD + col));
                ldsm4_t(tl, vcur_u + 2*(1*ASLAB + r*APAD + col));
                mma16816(oacc[2*jp],   pa, th);
                mma16816(oacc[2*jp],   pa, tl);
                mma16816(oacc[2*jp],   pl, th);
                mma16816(oacc[2*jp+1], pa, th+2);
                mma16816(oacc[2*jp+1], pa, tl+2);
                mma16816(oacc[2*jp+1], pl, th+2);
            }
        }

        if (pf) {
            *(uint4*)(sm + (4 + 2*nxt)*ASLAB     + krow*APAD + kv*8) = pv[0];
            *(uint4*)(sm + (4 + 2*nxt + 1)*ASLAB + krow*APAD + kv*8) = pv[1];
        }
        __syncthreads();
    }

    // ---- epilogue: att = oacc / l -> bf16 hi/lo concat [b,s,h*64+dk] ----
    const float inv0 = 1.0f / lr0;
    const float inv1 = 1.0f / lr1;
    const size_t basea = ((size_t)(b*S_ + qr0))*D_ + h*DK_;
    const size_t baseb = ((size_t)(b*S_ + qr1))*D_ + h*DK_;
    #pragma unroll
    for (int nj = 0; nj < 8; nj++) {
        const int dk = nj*8 + cc*2;
        const float v00 = oacc[nj][0]*inv0, v01 = oacc[nj][1]*inv0;
        const float v10 = oacc[nj][2]*inv1, v11 = oacc[nj][3]*inv1;
        *(uint32_t*)&g_att_hi[basea + dk] = packbf(v00, v01);
        *(uint32_t*)&g_att_lo[basea + dk] = packbf(bfres(v00), bfres(v01));
        *(uint32_t*)&g_att_hi[baseb + dk] = packbf(v10, v11);
        *(uint32_t*)&g_att_lo[baseb + dk] = packbf(bfres(v10), bfres(v11));
    }
}

// ---------------------------------------------------------------------------
extern "C" void kernel_launch(void* const* d_in, const int* in_sizes, int n_in,
                              void* d_out, int out_size)
{
    const float* q    = (const float*)d_in[0];
    const float* k    = (const float*)d_in[1];
    const float* v    = (const float*)d_in[2];
    const int*   mask = (const int*)  d_in[3];
    const float* Wq   = (const float*)d_in[4];
    const float* bq   = (const float*)d_in[5];
    const float* Wk   = (const float*)d_in[6];
    const float* bk   = (const float*)d_in[7];
    const float* Wv   = (const float*)d_in[8];
    const float* bv   = (const float*)d_in[9];
    const float* Wo   = (const float*)d_in[10];
    const float* bo   = (const float*)d_in[11];
    float* out = (float*)d_out;

    static int configured = 0;
    if (!configured) {
        cudaFuncSetAttribute(qkv_mma_kernel, cudaFuncAttributeMaxDynamicSharedMemorySize, PROJ_SMEM);
        cudaFuncSetAttribute(out_mma_kernel, cudaFuncAttributeMaxDynamicSharedMemorySize, PROJ_SMEM);
        cudaFuncSetAttribute(attn_mma_kernel, cudaFuncAttributeMaxDynamicSharedMemorySize, ATT_SMEM);
        configured = 1;
    }

    // 1. QKV projections
    qkv_mma_kernel<<<dim3(D_/128, M_/128, 3), 512, PROJ_SMEM>>>(
        q, k, v, Wq, bq, Wk, bk, Wv, bv);

    // 2. Attention (256 q-rows per CTA)
    attn_mma_kernel<<<dim3(S_/256, B_*H_), 512, ATT_SMEM>>>(mask);

    // 3. Output projection
    out_mma_kernel<<<dim3(D_/128, M_/128), 512, PROJ_SMEM>>>(Wo, bo, out);
}

// round 9
// speedup vs baseline: 3.4708x; 1.0692x over previous
#include <cuda_runtime.h>
#include <cuda_bf16.h>
#include <cstdint>
#include <math.h>

#define B_ 2
#define S_ 2048
#define D_ 1024
#define H_ 16
#define DK_ 64
#define M_ (B_*S_)
#define NEGINF (-1000000000.0f)

// ---------------------------------------------------------------------------
// Scratch: 64 MiB total (proven-safe budget), all bf16 hi/lo pairs.
// ---------------------------------------------------------------------------
__device__ __nv_bfloat16 g_Qh_hi[M_*D_], g_Qh_lo[M_*D_];   // [bh][s][dk]
__device__ __nv_bfloat16 g_Kh_hi[M_*D_], g_Kh_lo[M_*D_];
__device__ __nv_bfloat16 g_Vh_hi[M_*D_], g_Vh_lo[M_*D_];
__device__ __nv_bfloat16 g_att_hi[M_*D_], g_att_lo[M_*D_]; // [m][d]

// ---------------------------------------------------------------------------
// PTX helpers (base sm_100-legal: ldmatrix + mma.sync + cp.async)
// ---------------------------------------------------------------------------
__device__ __forceinline__ uint32_t smem_u32(const void* p) {
    uint32_t a;
    asm("{ .reg .u64 t; cvta.to.shared.u64 t, %1; cvt.u32.u64 %0, t; }" : "=r"(a) : "l"(p));
    return a;
}
__device__ __forceinline__ void ldsm4(uint32_t* r, uint32_t addr) {
    asm volatile("ldmatrix.sync.aligned.m8n8.x4.shared.b16 {%0,%1,%2,%3}, [%4];"
        : "=r"(r[0]), "=r"(r[1]), "=r"(r[2]), "=r"(r[3]) : "r"(addr));
}
__device__ __forceinline__ void ldsm4_t(uint32_t* r, uint32_t addr) {
    asm volatile("ldmatrix.sync.aligned.m8n8.x4.trans.shared.b16 {%0,%1,%2,%3}, [%4];"
        : "=r"(r[0]), "=r"(r[1]), "=r"(r[2]), "=r"(r[3]) : "r"(addr));
}
__device__ __forceinline__ void mma16816(float* d, const uint32_t* a, const uint32_t* b) {
    asm volatile(
        "mma.sync.aligned.m16n8k16.row.col.f32.bf16.bf16.f32 "
        "{%0,%1,%2,%3}, {%4,%5,%6,%7}, {%8,%9}, {%0,%1,%2,%3};"
        : "+f"(d[0]), "+f"(d[1]), "+f"(d[2]), "+f"(d[3])
        : "r"(a[0]), "r"(a[1]), "r"(a[2]), "r"(a[3]), "r"(b[0]), "r"(b[1]));
}
__device__ __forceinline__ void cpa16(uint32_t s, const void* g) {
    asm volatile("cp.async.cg.shared.global [%0], [%1], 16;" :: "r"(s), "l"(g));
}
#define CPA_COMMIT() asm volatile("cp.async.commit_group;" ::: "memory")
#define CPA_WAIT0()  asm volatile("cp.async.wait_group 0;" ::: "memory")

__device__ __forceinline__ uint32_t packbf(float lo, float hi) {
    uint32_t r;
    asm("cvt.rn.bf16x2.f32 %0, %1, %2;" : "=r"(r) : "f"(hi), "f"(lo));
    return r;
}
__device__ __forceinline__ float bfres(float x) {
    return x - __bfloat162float(__float2bfloat16(x));
}
__device__ __forceinline__ void split4(float4 x, uint2& h, uint2& l) {
    h.x = packbf(x.x, x.y);  h.y = packbf(x.z, x.w);
    l.x = packbf(bfres(x.x), bfres(x.y));
    l.y = packbf(bfres(x.z), bfres(x.w));
}
__device__ __forceinline__ void sts_split4(__nv_bfloat16* hi, __nv_bfloat16* lo,
                                           int row, int v, int pad, float4 x) {
    uint2 h, l; split4(x, h, l);
    *(uint2*)(hi + row*pad + v*4) = h;
    *(uint2*)(lo + row*pad + v*4) = l;
}

// ---------------------------------------------------------------------------
// Projection GEMM: C[m,n] = sum_k A[m,k]*W[n,k] + bias[n]
// 128x128 block, BK=64, 512 threads (16 warps 4m x 4n, warp tile 32x32).
// ABF16=0: A fp32 split in-kernel (reg prefetch). ABF16=1: A bf16 via cp.async.
// ---------------------------------------------------------------------------
#define PPAD 72
#define PSLAB (128*PPAD)
#define PSTAGE (4*PSLAB)
#define PROJ_SMEM (2*PSTAGE*2)     // 147456 B

__device__ __forceinline__ void proj_mma_kk(uint32_t stage_u, int kk, int wm, int wn,
                                            int lane, float acc[2][4][4])
{
    uint32_t ah[2][4], al[2][4];
    #pragma unroll
    for (int mi = 0; mi < 2; mi++) {
        const int r   = wm*32 + mi*16 + (lane & 15);
        const int col = kk*16 + ((lane & 16) ? 8 : 0);
        ldsm4(ah[mi], stage_u + 2*(0*PSLAB + r*PPAD + col));
        ldsm4(al[mi], stage_u + 2*(1*PSLAB + r*PPAD + col));
    }
    #pragma unroll
    for (int jp = 0; jp < 2; jp++) {
        const int p   = lane >> 3;
        const int r   = wn*32 + jp*16 + ((p >= 2) ? 8 : 0) + (lane & 7);
        const int col = kk*16 + ((p & 1) ? 8 : 0);
        uint32_t th[4], tl[4];
        ldsm4(th, stage_u + 2*(2*PSLAB + r*PPAD + col));
        ldsm4(tl, stage_u + 2*(3*PSLAB + r*PPAD + col));
        #pragma unroll
        for (int mi = 0; mi < 2; mi++) {
            mma16816(acc[mi][2*jp],   ah[mi], th);
            mma16816(acc[mi][2*jp],   ah[mi], tl);
            mma16816(acc[mi][2*jp],   al[mi], th);
            mma16816(acc[mi][2*jp+1], ah[mi], th+2);
            mma16816(acc[mi][2*jp+1], ah[mi], tl+2);
            mma16816(acc[mi][2*jp+1], al[mi], th+2);
        }
    }
}

template<int MODE, int ABF16>
__device__ __forceinline__ void proj_gemm(const float* __restrict__ Af,
                                          const __nv_bfloat16* __restrict__ Ahi,
                                          const __nv_bfloat16* __restrict__ Alo,
                                          const float* __restrict__ W,
                                          const float* __restrict__ bias,
                                          float* __restrict__ Cf,
                                          __nv_bfloat16* __restrict__ Chi,
                                          __nv_bfloat16* __restrict__ Clo)
{
    extern __shared__ __nv_bfloat16 sm[];
    const uint32_t sb = smem_u32(sm);
    const int tid  = threadIdx.x;
    const int lane = tid & 31;
    const int wid  = tid >> 5;
    const int wm   = wid & 3;
    const int wn   = wid >> 2;
    const int m0 = blockIdx.y * 128;
    const int n0 = blockIdx.x * 128;

    float acc[2][4][4];
    #pragma unroll
    for (int mi = 0; mi < 2; mi++)
        #pragma unroll
        for (int nj = 0; nj < 4; nj++)
            #pragma unroll
            for (int e = 0; e < 4; e++) acc[mi][nj][e] = 0.0f;

    float4 paf[4], pw[4];

    // ---- prologue: chunk 0 -> stage 0 ----
    if (ABF16) {
        #pragma unroll
        for (int it = 0; it < 2; it++) {
            const int idx = tid + it*512;          // 0..1023
            const int row = idx >> 3, v = idx & 7;
            cpa16(sb + 2*(0*PSLAB + row*PPAD + v*8), Ahi + (size_t)(m0+row)*D_ + v*8);
            cpa16(sb + 2*(1*PSLAB + row*PPAD + v*8), Alo + (size_t)(m0+row)*D_ + v*8);
        }
        CPA_COMMIT();
    } else {
        #pragma unroll
        for (int it = 0; it < 4; it++) {
            const int idx = tid + it*512;          // 0..2047
            const int row = idx >> 4, v = idx & 15;
            paf[it] = *((const float4*)(Af + (size_t)(m0+row)*D_) + v);
            sts_split4(sm + 0*PSLAB, sm + 1*PSLAB, row, v, PPAD, paf[it]);
        }
    }
    #pragma unroll
    for (int it = 0; it < 4; it++) {
        const int idx = tid + it*512;
        const int row = idx >> 4, v = idx & 15;
        pw[it] = *((const float4*)(W + (size_t)(n0+row)*D_) + v);
        sts_split4(sm + 2*PSLAB, sm + 3*PSLAB, row, v, PPAD, pw[it]);
    }
    if (ABF16) CPA_WAIT0();
    __syncthreads();

    for (int c = 0; c < 16; c++) {
        const int cur = c & 1;
        const int nxt = cur ^ 1;
        const uint32_t scur_u = sb + 2*(cur*PSTAGE);
        const uint32_t snx_u  = sb + 2*(nxt*PSTAGE);
        __nv_bfloat16* snx = sm + nxt*PSTAGE;
        const int k1 = (c + 1) * 64;
        const bool pf = (c < 15);

        if (pf) {
            if (ABF16) {
                #pragma unroll
                for (int it = 0; it < 2; it++) {
                    const int idx = tid + it*512;
                    const int row = idx >> 3, v = idx & 7;
                    cpa16(snx_u + 2*(0*PSLAB + row*PPAD + v*8),
                          Ahi + (size_t)(m0+row)*D_ + k1 + v*8);
                    cpa16(snx_u + 2*(1*PSLAB + row*PPAD + v*8),
                          Alo + (size_t)(m0+row)*D_ + k1 + v*8);
                }
                CPA_COMMIT();
            } else {
                #pragma unroll
                for (int it = 0; it < 4; it++) {
                    const int idx = tid + it*512;
                    const int row = idx >> 4, v = idx & 15;
                    paf[it] = *((const float4*)(Af + (size_t)(m0+row)*D_ + k1) + v);
                }
            }
        }
        proj_mma_kk(scur_u, 0, wm, wn, lane, acc);
        proj_mma_kk(scur_u, 1, wm, wn, lane, acc);
        if (pf) {
            if (!ABF16) {
                #pragma unroll
                for (int it = 0; it < 4; it++) {
                    const int idx = tid + it*512;
                    const int row = idx >> 4, v = idx & 15;
                    sts_split4(snx + 0*PSLAB, snx + 1*PSLAB, row, v, PPAD, paf[it]);
                }
            }
            #pragma unroll
            for (int it = 0; it < 4; it++) {
                const int idx = tid + it*512;
                const int row = idx >> 4, v = idx & 15;
                pw[it] = *((const float4*)(W + (size_t)(n0+row)*D_ + k1) + v);
            }
        }
        proj_mma_kk(scur_u, 2, wm, wn, lane, acc);
        proj_mma_kk(scur_u, 3, wm, wn, lane, acc);
        if (pf) {
            #pragma unroll
            for (int it = 0; it < 4; it++) {
                const int idx = tid + it*512;
                const int row = idx >> 4, v = idx & 15;
                sts_split4(snx + 2*PSLAB, snx + 3*PSLAB, row, v, PPAD, pw[it]);
            }
            if (ABF16) CPA_WAIT0();
        }
        __syncthreads();
    }

    // ---- epilogue ----
    const int g  = lane >> 2;
    const int cc = lane & 3;
    #pragma unroll
    for (int mi = 0; mi < 2; mi++) {
        const int ra = m0 + wm*32 + mi*16 + g;
        const int rb = ra + 8;
        #pragma unroll
        for (int nj = 0; nj < 4; nj++) {
            const int col = n0 + wn*32 + nj*8 + cc*2;
            const float b0 = bias[col], b1 = bias[col+1];
            const float v00 = acc[mi][nj][0] + b0, v01 = acc[mi][nj][1] + b1;
            const float v10 = acc[mi][nj][2] + b0, v11 = acc[mi][nj][3] + b1;
            if (MODE == 1) {
                const int h = col >> 6, dk = col & 63;
                const int ba = ra >> 11, sa = ra & (S_-1);
                const int bb = rb >> 11, sb2 = rb & (S_-1);
                const size_t ia = (((size_t)ba*H_ + h)*S_ + sa)*DK_ + dk;
                const size_t ib = (((size_t)bb*H_ + h)*S_ + sb2)*DK_ + dk;
                *(uint32_t*)&Chi[ia] = packbf(v00, v01);
                *(uint32_t*)&Clo[ia] = packbf(bfres(v00), bfres(v01));
                *(uint32_t*)&Chi[ib] = packbf(v10, v11);
                *(uint32_t*)&Clo[ib] = packbf(bfres(v10), bfres(v11));
            } else {
                *(float2*)&Cf[(size_t)ra*D_ + col] = make_float2(v00, v01);
                *(float2*)&Cf[(size_t)rb*D_ + col] = make_float2(v10, v11);
            }
        }
    }
}

__global__ void __launch_bounds__(512, 1)
qkv_mma_kernel(const float* __restrict__ q, const float* __restrict__ k,
               const float* __restrict__ v,
               const float* __restrict__ Wq, const float* __restrict__ bq,
               const float* __restrict__ Wk, const float* __restrict__ bk,
               const float* __restrict__ Wv, const float* __restrict__ bv)
{
    const int z = blockIdx.z;
    if (z == 0)      proj_gemm<1,0>(q, nullptr, nullptr, Wq, bq, nullptr, g_Qh_hi, g_Qh_lo);
    else if (z == 1) proj_gemm<1,0>(k, nullptr, nullptr, Wk, bk, nullptr, g_Kh_hi, g_Kh_lo);
    else             proj_gemm<1,0>(v, nullptr, nullptr, Wv, bv, nullptr, g_Vh_hi, g_Vh_lo);
}

__global__ void __launch_bounds__(512, 1)
out_mma_kernel(const float* __restrict__ Wo, const float* __restrict__ bo,
               float* __restrict__ out)
{
    proj_gemm<0,1>(nullptr, g_att_hi, g_att_lo, Wo, bo, out, nullptr, nullptr);
}

// ---------------------------------------------------------------------------
// Flash attention on mma.sync. 256 threads, 8 warps x m32 = 256 q rows/CTA.
// Q persistent in smem (re-ldsm per kk); K/V double-buffered via cp.async.
// B-fragments reused across 2 m-frags (MMA:ldsm ratio 4-6).
// Mask: mask[b, q] masks QUERY rows (broadcast over keys).
// ---------------------------------------------------------------------------
#define APAD 72
#define AQSLAB (256*APAD)              // 18432 elems per Q slab (hi, lo)
#define ASLAB  (64*APAD)               // 4608 elems per KV slab
#define AKV0   (2*AQSLAB)              // KV region base (elems)
// KV slabs within region: 0=K0h 1=K0l 2=K1h 3=K1l 4=V0h 5=V0l 6=V1h 7=V1l
#define ATT_SMEM ((2*AQSLAB + 8*ASLAB)*2)   // 147456 B

__global__ void __launch_bounds__(256, 1)
attn_mma_kernel(const int* __restrict__ mask)
{
    extern __shared__ __nv_bfloat16 sm[];
    const uint32_t sb = smem_u32(sm);
    const int tid  = threadIdx.x;
    const int lane = tid & 31;
    const int wid  = tid >> 5;       // 0..7
    const int g    = lane >> 2;
    const int cc   = lane & 3;

    const int bh = blockIdx.y;
    const int b  = bh >> 4;
    const int h  = bh & 15;
    const int q0 = blockIdx.x * 256;

    const __nv_bfloat16* Qhi = g_Qh_hi + (size_t)bh*S_*DK_;
    const __nv_bfloat16* Qlo = g_Qh_lo + (size_t)bh*S_*DK_;
    const __nv_bfloat16* Khi = g_Kh_hi + (size_t)bh*S_*DK_;
    const __nv_bfloat16* Klo = g_Kh_lo + (size_t)bh*S_*DK_;
    const __nv_bfloat16* Vhi = g_Vh_hi + (size_t)bh*S_*DK_;
    const __nv_bfloat16* Vlo = g_Vh_lo + (size_t)bh*S_*DK_;
    const int* mp = mask + b*S_;

    // ---- issue KV tile 0 via cp.async; load Q tile concurrently ----
    {
        #pragma unroll
        for (int i = 0; i < 2; i++) {
            const int idx = tid + i*256;       // 0..511
            const int row = idx >> 3, v = idx & 7;
            const uint32_t so = sb + 2*(AKV0 + row*APAD + v*8);
            const size_t  go = (size_t)row*DK_ + v*8;
            cpa16(so + 2*(0*ASLAB), Khi + go);
            cpa16(so + 2*(1*ASLAB), Klo + go);
            cpa16(so + 2*(4*ASLAB), Vhi + go);
            cpa16(so + 2*(5*ASLAB), Vlo + go);
        }
        CPA_COMMIT();
    }
    #pragma unroll
    for (int it = 0; it < 8; it++) {
        const int idx = tid + it*256;          // 0..2047
        const int row = idx >> 3, v = idx & 7;
        *(uint4*)(sm + 0      + row*APAD + v*8) =
            *((const uint4*)(Qhi + (size_t)(q0+row)*DK_) + v);
        *(uint4*)(sm + AQSLAB + row*APAD + v*8) =
            *((const uint4*)(Qlo + (size_t)(q0+row)*DK_) + v);
    }
    CPA_WAIT0();
    __syncthreads();

    const int qra0 = q0 + wid*32 + g;          // mi=0 rows: qra0, qra0+8
    const int qra1 = qra0 + 16;                // mi=1 rows: qra1, qra1+8
    bool msk[2][2];
    msk[0][0] = (mp[qra0] == 0);      msk[0][1] = (mp[qra0 + 8] == 0);
    msk[1][0] = (mp[qra1] == 0);      msk[1][1] = (mp[qra1 + 8] == 0);

    float mr[2][2], lr[2][2];
    #pragma unroll
    for (int mi = 0; mi < 2; mi++) { mr[mi][0] = mr[mi][1] = -1e30f; lr[mi][0] = lr[mi][1] = 0.0f; }

    float oacc[2][8][4];
    #pragma unroll
    for (int mi = 0; mi < 2; mi++)
        #pragma unroll
        for (int nj = 0; nj < 8; nj++)
            #pragma unroll
            for (int e = 0; e < 4; e++) oacc[mi][nj][e] = 0.0f;

    for (int t = 0; t < 32; t++) {
        const int cur = t & 1;
        const int nxt = cur ^ 1;
        const bool pf = (t + 1 < 32);
        const uint32_t kcur_u = sb + 2*(AKV0 + (2*cur)*ASLAB);
        const uint32_t vcur_u = sb + 2*(AKV0 + (4 + 2*cur)*ASLAB);

        // issue cp.async for KV tile t+1 into nxt buffers
        if (pf) {
            const size_t base = (size_t)((t + 1)*64)*DK_;
            #pragma unroll
            for (int i = 0; i < 2; i++) {
                const int idx = tid + i*256;
                const int row = idx >> 3, v = idx & 7;
                const uint32_t so = sb + 2*(AKV0 + row*APAD + v*8);
                const size_t  go = base + (size_t)row*DK_ + v*8;
                cpa16(so + 2*((2*nxt)*ASLAB),     Khi + go);
                cpa16(so + 2*((2*nxt+1)*ASLAB),   Klo + go);
                cpa16(so + 2*((4+2*nxt)*ASLAB),   Vhi + go);
                cpa16(so + 2*((4+2*nxt+1)*ASLAB), Vlo + go);
            }
            CPA_COMMIT();
        }

        // ---- S = Q K^T ----
        float sacc[2][8][4];
        #pragma unroll
        for (int mi = 0; mi < 2; mi++)
            #pragma unroll
            for (int nj = 0; nj < 8; nj++)
                #pragma unroll
                for (int e = 0; e < 4; e++) sacc[mi][nj][e] = 0.0f;

        #pragma unroll
        for (int kk = 0; kk < 4; kk++) {
            uint32_t aqh[2][4], aql[2][4];
            #pragma unroll
            for (int mi = 0; mi < 2; mi++) {
                const int r   = wid*32 + mi*16 + (lane & 15);
                const int col = kk*16 + ((lane & 16) ? 8 : 0);
                ldsm4(aqh[mi], sb + 2*(0      + r*APAD + col));
                ldsm4(aql[mi], sb + 2*(AQSLAB + r*APAD + col));
            }
            #pragma unroll
            for (int jp = 0; jp < 4; jp++) {
                const int p   = lane >> 3;
                const int r   = jp*16 + ((p >= 2) ? 8 : 0) + (lane & 7);
                const int col = kk*16 + ((p & 1) ? 8 : 0);
                uint32_t th[4], tl[4];
                ldsm4(th, kcur_u + 2*(0*ASLAB + r*APAD + col));
                ldsm4(tl, kcur_u + 2*(1*ASLAB + r*APAD + col));
                #pragma unroll
                for (int mi = 0; mi < 2; mi++) {
                    mma16816(sacc[mi][2*jp],   aqh[mi], th);
                    mma16816(sacc[mi][2*jp],   aqh[mi], tl);
                    mma16816(sacc[mi][2*jp],   aql[mi], th);
                    mma16816(sacc[mi][2*jp+1], aqh[mi], th+2);
                    mma16816(sacc[mi][2*jp+1], aqh[mi], tl+2);
                    mma16816(sacc[mi][2*jp+1], aql[mi], th+2);
                }
            }
        }

        // ---- mask + online softmax (per mi) ----
        #pragma unroll
        for (int mi = 0; mi < 2; mi++) {
            if (msk[mi][0]) {
                #pragma unroll
                for (int nj = 0; nj < 8; nj++) { sacc[mi][nj][0] = NEGINF; sacc[mi][nj][1] = NEGINF; }
            }
            if (msk[mi][1]) {
                #pragma unroll
                for (int nj = 0; nj < 8; nj++) { sacc[mi][nj][2] = NEGINF; sacc[mi][nj][3] = NEGINF; }
            }

            float mx0 = -1e30f, mx1 = -1e30f;
            #pragma unroll
            for (int nj = 0; nj < 8; nj++) {
                mx0 = fmaxf(mx0, fmaxf(sacc[mi][nj][0], sacc[mi][nj][1]));
                mx1 = fmaxf(mx1, fmaxf(sacc[mi][nj][2], sacc[mi][nj][3]));
            }
            mx0 = fmaxf(mx0, __shfl_xor_sync(0xffffffffu, mx0, 1));
            mx0 = fmaxf(mx0, __shfl_xor_sync(0xffffffffu, mx0, 2));
            mx1 = fmaxf(mx1, __shfl_xor_sync(0xffffffffu, mx1, 1));
            mx1 = fmaxf(mx1, __shfl_xor_sync(0xffffffffu, mx1, 2));

            const float mn0 = fmaxf(mr[mi][0], mx0);
            const float mn1 = fmaxf(mr[mi][1], mx1);
            const float al0 = __expf(mr[mi][0] - mn0);
            const float al1 = __expf(mr[mi][1] - mn1);
            mr[mi][0] = mn0; mr[mi][1] = mn1;

            float rs0 = 0.0f, rs1 = 0.0f;
            #pragma unroll
            for (int nj = 0; nj < 8; nj++) {
                const float p0 = __expf(sacc[mi][nj][0] - mn0);
                const float p1 = __expf(sacc[mi][nj][1] - mn0);
                const float p2 = __expf(sacc[mi][nj][2] - mn1);
                const float p3 = __expf(sacc[mi][nj][3] - mn1);
                sacc[mi][nj][0] = p0; sacc[mi][nj][1] = p1;
                sacc[mi][nj][2] = p2; sacc[mi][nj][3] = p3;
                rs0 += p0 + p1; rs1 += p2 + p3;
            }
            rs0 += __shfl_xor_sync(0xffffffffu, rs0, 1);
            rs0 += __shfl_xor_sync(0xffffffffu, rs0, 2);
            rs1 += __shfl_xor_sync(0xffffffffu, rs1, 1);
            rs1 += __shfl_xor_sync(0xffffffffu, rs1, 2);
            lr[mi][0] = lr[mi][0]*al0 + rs0;
            lr[mi][1] = lr[mi][1]*al1 + rs1;

            #pragma unroll
            for (int nj = 0; nj < 8; nj++) {
                oacc[mi][nj][0] *= al0; oacc[mi][nj][1] *= al0;
                oacc[mi][nj][2] *= al1; oacc[mi][nj][3] *= al1;
            }
        }

        // ---- O += P V ----
        #pragma unroll
        for (int t4 = 0; t4 < 4; t4++) {
            uint32_t pa[2][4], pl[2][4];
            #pragma unroll
            for (int mi = 0; mi < 2; mi++) {
                const float p00 = sacc[mi][2*t4][0],   p01 = sacc[mi][2*t4][1];
                const float p02 = sacc[mi][2*t4][2],   p03 = sacc[mi][2*t4][3];
                const float p10 = sacc[mi][2*t4+1][0], p11 = sacc[mi][2*t4+1][1];
                const float p12 = sacc[mi][2*t4+1][2], p13 = sacc[mi][2*t4+1][3];
                pa[mi][0] = packbf(p00, p01); pa[mi][1] = packbf(p02, p03);
                pa[mi][2] = packbf(p10, p11); pa[mi][3] = packbf(p12, p13);
                pl[mi][0] = packbf(bfres(p00), bfres(p01)); pl[mi][1] = packbf(bfres(p02), bfres(p03));
                pl[mi][2] = packbf(bfres(p10), bfres(p11)); pl[mi][3] = packbf(bfres(p12), bfres(p13));
            }
            #pragma unroll
            for (int jp = 0; jp < 4; jp++) {
                const int p   = lane >> 3;
                const int r   = t4*16 + ((p & 1) ? 8 : 0) + (lane & 7);
                const int col = jp*16 + ((p >= 2) ? 8 : 0);
                uint32_t th[4], tl[4];
                ldsm4_t(th, vcur_u + 2*(0*ASLAB + r*APAD + col));
                ldsm4_t(tl, vcur_u + 2*(1*ASLAB + r*APAD + col));
                #pragma unroll
                for (int mi = 0; mi < 2; mi++) {
                    mma16816(oacc[mi][2*jp],   pa[mi], th);
                    mma16816(oacc[mi][2*jp],   pa[mi], tl);
                    mma16816(oacc[mi][2*jp],   pl[mi], th);
                    mma16816(oacc[mi][2*jp+1], pa[mi], th+2);
                    mma16816(oacc[mi][2*jp+1], pa[mi], tl+2);
                    mma16816(oacc[mi][2*jp+1], pl[mi], th+2);
                }
            }
        }

        if (pf) CPA_WAIT0();
        __syncthreads();
    }

    // ---- epilogue: att = oacc / l -> bf16 hi/lo concat [b,s,h*64+dk] ----
    #pragma unroll
    for (int mi = 0; mi < 2; mi++) {
        const int qa = (mi == 0) ? qra0 : qra1;
        const float inv0 = 1.0f / lr[mi][0];
        const float inv1 = 1.0f / lr[mi][1];
        const size_t basea = ((size_t)(b*S_ + qa))*D_ + h*DK_;
        const size_t baseb = ((size_t)(b*S_ + qa + 8))*D_ + h*DK_;
        #pragma unroll
        for (int nj = 0; nj < 8; nj++) {
            const int dk = nj*8 + cc*2;
            const float v00 = oacc[mi][nj][0]*inv0, v01 = oacc[mi][nj][1]*inv0;
            const float v10 = oacc[mi][nj][2]*inv1, v11 = oacc[mi][nj][3]*inv1;
            *(uint32_t*)&g_att_hi[basea + dk] = packbf(v00, v01);
            *(uint32_t*)&g_att_lo[basea + dk] = packbf(bfres(v00), bfres(v01));
            *(uint32_t*)&g_att_hi[baseb + dk] = packbf(v10, v11);
            *(uint32_t*)&g_att_lo[baseb + dk] = packbf(bfres(v10), bfres(v11));
        }
    }
}

// ---------------------------------------------------------------------------
extern "C" void kernel_launch(void* const* d_in, const int* in_sizes, int n_in,
                              void* d_out, int out_size)
{
    const float* q    = (const float*)d_in[0];
    const float* k    = (const float*)d_in[1];
    const float* v    = (const float*)d_in[2];
    const int*   mask = (const int*)  d_in[3];
    const float* Wq   = (const float*)d_in[4];
    const float* bq   = (const float*)d_in[5];
    const float* Wk   = (const float*)d_in[6];
    const float* bk   = (const float*)d_in[7];
    const float* Wv   = (const float*)d_in[8];
    const float* bv   = (const float*)d_in[9];
    const float* Wo   = (const float*)d_in[10];
    const float* bo   = (const float*)d_in[11];
    float* out = (float*)d_out;

    static int configured = 0;
    if (!configured) {
        cudaFuncSetAttribute(qkv_mma_kernel, cudaFuncAttributeMaxDynamicSharedMemorySize, PROJ_SMEM);
        cudaFuncSetAttribute(out_mma_kernel, cudaFuncAttributeMaxDynamicSharedMemorySize, PROJ_SMEM);
        cudaFuncSetAttribute(attn_mma_kernel, cudaFuncAttributeMaxDynamicSharedMemorySize, ATT_SMEM);
        configured = 1;
    }

    // 1. QKV projections
    qkv_mma_kernel<<<dim3(D_/128, M_/128, 3), 512, PROJ_SMEM>>>(
        q, k, v, Wq, bq, Wk, bk, Wv, bv);

    // 2. Attention (256 q-rows per CTA, m32 warps, cp.async KV pipeline)
    attn_mma_kernel<<<dim3(S_/256, B_*H_), 256, ATT_SMEM>>>(mask);

    // 3. Output projection
    out_mma_kernel<<<dim3(D_/128, M_/128), 512, PROJ_SMEM>>>(Wo, bo, out);
}

// round 10
// speedup vs baseline: 3.5262x; 1.0160x over previous
#include <cuda_runtime.h>
#include <cuda_bf16.h>
#include <cstdint>
#include <math.h>

#define B_ 2
#define S_ 2048
#define D_ 1024
#define H_ 16
#define DK_ 64
#define M_ (B_*S_)
#define NEGINF (-1000000000.0f)

// ---------------------------------------------------------------------------
// Scratch: 64 MiB total (proven-safe budget), all bf16 hi/lo pairs.
// ---------------------------------------------------------------------------
__device__ __nv_bfloat16 g_Qh_hi[M_*D_], g_Qh_lo[M_*D_];   // [bh][s][dk]
__device__ __nv_bfloat16 g_Kh_hi[M_*D_], g_Kh_lo[M_*D_];
__device__ __nv_bfloat16 g_Vh_hi[M_*D_], g_Vh_lo[M_*D_];
__device__ __nv_bfloat16 g_att_hi[M_*D_], g_att_lo[M_*D_]; // [m][d]

// ---------------------------------------------------------------------------
// PTX helpers (base sm_100-legal: ldmatrix + mma.sync + cp.async)
// ---------------------------------------------------------------------------
__device__ __forceinline__ uint32_t smem_u32(const void* p) {
    uint32_t a;
    asm("{ .reg .u64 t; cvta.to.shared.u64 t, %1; cvt.u32.u64 %0, t; }" : "=r"(a) : "l"(p));
    return a;
}
__device__ __forceinline__ void ldsm4(uint32_t* r, uint32_t addr) {
    asm volatile("ldmatrix.sync.aligned.m8n8.x4.shared.b16 {%0,%1,%2,%3}, [%4];"
        : "=r"(r[0]), "=r"(r[1]), "=r"(r[2]), "=r"(r[3]) : "r"(addr));
}
__device__ __forceinline__ void ldsm4_t(uint32_t* r, uint32_t addr) {
    asm volatile("ldmatrix.sync.aligned.m8n8.x4.trans.shared.b16 {%0,%1,%2,%3}, [%4];"
        : "=r"(r[0]), "=r"(r[1]), "=r"(r[2]), "=r"(r[3]) : "r"(addr));
}
__device__ __forceinline__ void mma16816(float* d, const uint32_t* a, const uint32_t* b) {
    asm volatile(
        "mma.sync.aligned.m16n8k16.row.col.f32.bf16.bf16.f32 "
        "{%0,%1,%2,%3}, {%4,%5,%6,%7}, {%8,%9}, {%0,%1,%2,%3};"
        : "+f"(d[0]), "+f"(d[1]), "+f"(d[2]), "+f"(d[3])
        : "r"(a[0]), "r"(a[1]), "r"(a[2]), "r"(a[3]), "r"(b[0]), "r"(b[1]));
}
__device__ __forceinline__ void cpa16(uint32_t s, const void* g) {
    asm volatile("cp.async.cg.shared.global [%0], [%1], 16;" :: "r"(s), "l"(g));
}
#define CPA_COMMIT() asm volatile("cp.async.commit_group;" ::: "memory")
#define CPA_WAIT0()  asm volatile("cp.async.wait_group 0;" ::: "memory")

__device__ __forceinline__ uint32_t packbf(float lo, float hi) {
    uint32_t r;
    asm("cvt.rn.bf16x2.f32 %0, %1, %2;" : "=r"(r) : "f"(hi), "f"(lo));
    return r;
}
__device__ __forceinline__ float bfres(float x) {
    return x - __bfloat162float(__float2bfloat16(x));
}
__device__ __forceinline__ void split4(float4 x, uint2& h, uint2& l) {
    h.x = packbf(x.x, x.y);  h.y = packbf(x.z, x.w);
    l.x = packbf(bfres(x.x), bfres(x.y));
    l.y = packbf(bfres(x.z), bfres(x.w));
}
__device__ __forceinline__ void sts_split4(__nv_bfloat16* hi, __nv_bfloat16* lo,
                                           int row, int v, int pad, float4 x) {
    uint2 h, l; split4(x, h, l);
    *(uint2*)(hi + row*pad + v*4) = h;
    *(uint2*)(lo + row*pad + v*4) = l;
}

// ---------------------------------------------------------------------------
// Projection GEMM: C[m,n] = sum_k A[m,k]*W[n,k] + bias[n]
// 128x256 block, BK=64, 512 threads (16 warps 4m x 4n, warp tile 32x64).
// MMA:ldsm ratio 4.0. Double-buffered smem + staged register prefetch.
// ABF16=0: A fp32 split in-kernel. ABF16=1: A bf16 hi/lo via cp.async.
// ---------------------------------------------------------------------------
#define PPAD 72
#define PASLAB (128*PPAD)              // A slab elems
#define PWSLAB (256*PPAD)              // W slab elems
#define PSTAGE (2*PASLAB + 2*PWSLAB)   // stage elems
#define POFF_W (2*PASLAB)              // W hi slab offset in stage
#define PROJ_SMEM (2*PSTAGE*2)         // 221184 B

__device__ __forceinline__ void proj_mma_kk(uint32_t stage_u, int kk, int wm, int wn,
                                            int lane, float acc[2][8][4])
{
    uint32_t ah[2][4], al[2][4];
    #pragma unroll
    for (int mi = 0; mi < 2; mi++) {
        const int r   = wm*32 + mi*16 + (lane & 15);
        const int col = kk*16 + ((lane & 16) ? 8 : 0);
        ldsm4(ah[mi], stage_u + 2*(0*PASLAB + r*PPAD + col));
        ldsm4(al[mi], stage_u + 2*(1*PASLAB + r*PPAD + col));
    }
    #pragma unroll
    for (int jp = 0; jp < 4; jp++) {
        const int p   = lane >> 3;
        const int r   = wn*64 + jp*16 + ((p >= 2) ? 8 : 0) + (lane & 7);
        const int col = kk*16 + ((p & 1) ? 8 : 0);
        uint32_t th[4], tl[4];
        ldsm4(th, stage_u + 2*(POFF_W + 0*PWSLAB + r*PPAD + col));
        ldsm4(tl, stage_u + 2*(POFF_W + 1*PWSLAB + r*PPAD + col));
        #pragma unroll
        for (int mi = 0; mi < 2; mi++) {
            mma16816(acc[mi][2*jp],   ah[mi], th);
            mma16816(acc[mi][2*jp],   ah[mi], tl);
            mma16816(acc[mi][2*jp],   al[mi], th);
            mma16816(acc[mi][2*jp+1], ah[mi], th+2);
            mma16816(acc[mi][2*jp+1], ah[mi], tl+2);
            mma16816(acc[mi][2*jp+1], al[mi], th+2);
        }
    }
}

template<int MODE, int ABF16>
__device__ __forceinline__ void proj_gemm(const float* __restrict__ Af,
                                          const __nv_bfloat16* __restrict__ Ahi,
                                          const __nv_bfloat16* __restrict__ Alo,
                                          const float* __restrict__ W,
                                          const float* __restrict__ bias,
                                          float* __restrict__ Cf,
                                          __nv_bfloat16* __restrict__ Chi,
                                          __nv_bfloat16* __restrict__ Clo)
{
    extern __shared__ __nv_bfloat16 sm[];
    const uint32_t sb = smem_u32(sm);
    const int tid  = threadIdx.x;
    const int lane = tid & 31;
    const int wid  = tid >> 5;
    const int wm   = wid & 3;
    const int wn   = wid >> 2;
    const int m0 = blockIdx.y * 128;
    const int n0 = blockIdx.x * 256;

    // A-load indices: 128 rows x 16 f4 = 2048 -> 4/thread
    const int arow = tid >> 4;          // base row (0..31), +it*32
    const int av   = tid & 15;
    // W-load indices: 256 rows x 16 f4 = 4096 -> 8/thread (two batches of 4)
    const int wrow = tid >> 4;
    const int wv   = tid & 15;

    float acc[2][8][4];
    #pragma unroll
    for (int mi = 0; mi < 2; mi++)
        #pragma unroll
        for (int nj = 0; nj < 8; nj++)
            #pragma unroll
            for (int e = 0; e < 4; e++) acc[mi][nj][e] = 0.0f;

    float4 pa[4], pw[4];

    // ---- prologue: chunk 0 -> stage 0 ----
    if (ABF16) {
        #pragma unroll
        for (int it = 0; it < 2; it++) {
            const int idx = tid + it*512;          // 0..1023
            const int row = idx >> 3, v = idx & 7;
            cpa16(sb + 2*(0*PASLAB + row*PPAD + v*8), Ahi + (size_t)(m0+row)*D_ + v*8);
            cpa16(sb + 2*(1*PASLAB + row*PPAD + v*8), Alo + (size_t)(m0+row)*D_ + v*8);
        }
        CPA_COMMIT();
    } else {
        #pragma unroll
        for (int it = 0; it < 4; it++) {
            const int row = arow + it*32;
            float4 x = *((const float4*)(Af + (size_t)(m0+row)*D_) + av);
            sts_split4(sm + 0*PASLAB, sm + 1*PASLAB, row, av, PPAD, x);
        }
    }
    #pragma unroll
    for (int it = 0; it < 8; it++) {
        const int row = wrow + it*32;
        float4 x = *((const float4*)(W + (size_t)(n0+row)*D_) + wv);
        sts_split4(sm + POFF_W, sm + POFF_W + PWSLAB, row, wv, PPAD, x);
    }
    if (ABF16) CPA_WAIT0();
    __syncthreads();

    for (int c = 0; c < 16; c++) {
        const int cur = c & 1;
        const int nxt = cur ^ 1;
        const uint32_t scur_u = sb + 2*(cur*PSTAGE);
        const uint32_t snx_u  = sb + 2*(nxt*PSTAGE);
        __nv_bfloat16* snx = sm + nxt*PSTAGE;
        const int k1 = (c + 1) * 64;
        const bool pf = (c < 15);

        // prefetch A(c+1)
        if (pf) {
            if (ABF16) {
                #pragma unroll
                for (int it = 0; it < 2; it++) {
                    const int idx = tid + it*512;
                    const int row = idx >> 3, v = idx & 7;
                    cpa16(snx_u + 2*(0*PASLAB + row*PPAD + v*8),
                          Ahi + (size_t)(m0+row)*D_ + k1 + v*8);
                    cpa16(snx_u + 2*(1*PASLAB + row*PPAD + v*8),
                          Alo + (size_t)(m0+row)*D_ + k1 + v*8);
                }
                CPA_COMMIT();
            } else {
                #pragma unroll
                for (int it = 0; it < 4; it++) {
                    const int row = arow + it*32;
                    pa[it] = *((const float4*)(Af + (size_t)(m0+row)*D_ + k1) + av);
                }
            }
        }
        proj_mma_kk(scur_u, 0, wm, wn, lane, acc);
        if (pf) {
            if (!ABF16) {
                #pragma unroll
                for (int it = 0; it < 4; it++)
                    sts_split4(snx + 0*PASLAB, snx + 1*PASLAB, arow + it*32, av, PPAD, pa[it]);
            }
            #pragma unroll
            for (int it = 0; it < 4; it++) {
                const int row = wrow + it*32;
                pw[it] = *((const float4*)(W + (size_t)(n0+row)*D_ + k1) + wv);
            }
        }
        proj_mma_kk(scur_u, 1, wm, wn, lane, acc);
        if (pf) {
            #pragma unroll
            for (int it = 0; it < 4; it++)
                sts_split4(snx + POFF_W, snx + POFF_W + PWSLAB, wrow + it*32, wv, PPAD, pw[it]);
            #pragma unroll
            for (int it = 0; it < 4; it++) {
                const int row = wrow + (it + 4)*32;
                pw[it] = *((const float4*)(W + (size_t)(n0+row)*D_ + k1) + wv);
            }
        }
        proj_mma_kk(scur_u, 2, wm, wn, lane, acc);
        if (pf) {
            #pragma unroll
            for (int it = 0; it < 4; it++)
                sts_split4(snx + POFF_W, snx + POFF_W + PWSLAB, wrow + (it + 4)*32, wv, PPAD, pw[it]);
        }
        proj_mma_kk(scur_u, 3, wm, wn, lane, acc);
        if (pf && ABF16) CPA_WAIT0();
        __syncthreads();
    }

    // ---- epilogue ----
    const int g  = lane >> 2;
    const int cc = lane & 3;
    #pragma unroll
    for (int mi = 0; mi < 2; mi++) {
        const int ra = m0 + wm*32 + mi*16 + g;
        const int rb = ra + 8;
        #pragma unroll
        for (int nj = 0; nj < 8; nj++) {
            const int col = n0 + wn*64 + nj*8 + cc*2;
            const float b0 = bias[col], b1 = bias[col+1];
            const float v00 = acc[mi][nj][0] + b0, v01 = acc[mi][nj][1] + b1;
            const float v10 = acc[mi][nj][2] + b0, v11 = acc[mi][nj][3] + b1;
            if (MODE == 1) {
                const int h = col >> 6, dk = col & 63;
                const int ba = ra >> 11, sa = ra & (S_-1);
                const int bb = rb >> 11, sb2 = rb & (S_-1);
                const size_t ia = (((size_t)ba*H_ + h)*S_ + sa)*DK_ + dk;
                const size_t ib = (((size_t)bb*H_ + h)*S_ + sb2)*DK_ + dk;
                *(uint32_t*)&Chi[ia] = packbf(v00, v01);
                *(uint32_t*)&Clo[ia] = packbf(bfres(v00), bfres(v01));
                *(uint32_t*)&Chi[ib] = packbf(v10, v11);
                *(uint32_t*)&Clo[ib] = packbf(bfres(v10), bfres(v11));
            } else {
                *(float2*)&Cf[(size_t)ra*D_ + col] = make_float2(v00, v01);
                *(float2*)&Cf[(size_t)rb*D_ + col] = make_float2(v10, v11);
            }
        }
    }
}

__global__ void __launch_bounds__(512, 1)
qkv_mma_kernel(const float* __restrict__ q, const float* __restrict__ k,
               const float* __restrict__ v,
               const float* __restrict__ Wq, const float* __restrict__ bq,
               const float* __restrict__ Wk, const float* __restrict__ bk,
               const float* __restrict__ Wv, const float* __restrict__ bv)
{
    const int z = blockIdx.z;
    if (z == 0)      proj_gemm<1,0>(q, nullptr, nullptr, Wq, bq, nullptr, g_Qh_hi, g_Qh_lo);
    else if (z == 1) proj_gemm<1,0>(k, nullptr, nullptr, Wk, bk, nullptr, g_Kh_hi, g_Kh_lo);
    else             proj_gemm<1,0>(v, nullptr, nullptr, Wv, bv, nullptr, g_Vh_hi, g_Vh_lo);
}

__global__ void __launch_bounds__(512, 1)
out_mma_kernel(const float* __restrict__ Wo, const float* __restrict__ bo,
               float* __restrict__ out)
{
    proj_gemm<0,1>(nullptr, g_att_hi, g_att_lo, Wo, bo, out, nullptr, nullptr);
}

// ---------------------------------------------------------------------------
// Flash attention on mma.sync (unchanged from R9).
// 256 threads, 8 warps x m32 = 256 q rows/CTA. Q persistent in smem;
// K/V double-buffered via cp.async. Mask: mask[b, q] masks QUERY rows.
// ---------------------------------------------------------------------------
#define APAD 72
#define AQSLAB (256*APAD)
#define ASLAB  (64*APAD)
#define AKV0   (2*AQSLAB)
#define ATT_SMEM ((2*AQSLAB + 8*ASLAB)*2)   // 147456 B

__global__ void __launch_bounds__(256, 1)
attn_mma_kernel(const int* __restrict__ mask)
{
    extern __shared__ __nv_bfloat16 sm[];
    const uint32_t sb = smem_u32(sm);
    const int tid  = threadIdx.x;
    const int lane = tid & 31;
    const int wid  = tid >> 5;
    const int g    = lane >> 2;
    const int cc   = lane & 3;

    const int bh = blockIdx.y;
    const int b  = bh >> 4;
    const int h  = bh & 15;
    const int q0 = blockIdx.x * 256;

    const __nv_bfloat16* Qhi = g_Qh_hi + (size_t)bh*S_*DK_;
    const __nv_bfloat16* Qlo = g_Qh_lo + (size_t)bh*S_*DK_;
    const __nv_bfloat16* Khi = g_Kh_hi + (size_t)bh*S_*DK_;
    const __nv_bfloat16* Klo = g_Kh_lo + (size_t)bh*S_*DK_;
    const __nv_bfloat16* Vhi = g_Vh_hi + (size_t)bh*S_*DK_;
    const __nv_bfloat16* Vlo = g_Vh_lo + (size_t)bh*S_*DK_;
    const int* mp = mask + b*S_;

    {
        #pragma unroll
        for (int i = 0; i < 2; i++) {
            const int idx = tid + i*256;
            const int row = idx >> 3, v = idx & 7;
            const uint32_t so = sb + 2*(AKV0 + row*APAD + v*8);
            const size_t  go = (size_t)row*DK_ + v*8;
            cpa16(so + 2*(0*ASLAB), Khi + go);
            cpa16(so + 2*(1*ASLAB), Klo + go);
            cpa16(so + 2*(4*ASLAB), Vhi + go);
            cpa16(so + 2*(5*ASLAB), Vlo + go);
        }
        CPA_COMMIT();
    }
    #pragma unroll
    for (int it = 0; it < 8; it++) {
        const int idx = tid + it*256;
        const int row = idx >> 3, v = idx & 7;
        *(uint4*)(sm + 0      + row*APAD + v*8) =
            *((const uint4*)(Qhi + (size_t)(q0+row)*DK_) + v);
        *(uint4*)(sm + AQSLAB + row*APAD + v*8) =
            *((const uint4*)(Qlo + (size_t)(q0+row)*DK_) + v);
    }
    CPA_WAIT0();
    __syncthreads();

    const int qra0 = q0 + wid*32 + g;
    const int qra1 = qra0 + 16;
    bool msk[2][2];
    msk[0][0] = (mp[qra0] == 0);      msk[0][1] = (mp[qra0 + 8] == 0);
    msk[1][0] = (mp[qra1] == 0);      msk[1][1] = (mp[qra1 + 8] == 0);

    float mr[2][2], lr[2][2];
    #pragma unroll
    for (int mi = 0; mi < 2; mi++) { mr[mi][0] = mr[mi][1] = -1e30f; lr[mi][0] = lr[mi][1] = 0.0f; }

    float oacc[2][8][4];
    #pragma unroll
    for (int mi = 0; mi < 2; mi++)
        #pragma unroll
        for (int nj = 0; nj < 8; nj++)
            #pragma unroll
            for (int e = 0; e < 4; e++) oacc[mi][nj][e] = 0.0f;

    for (int t = 0; t < 32; t++) {
        const int cur = t & 1;
        const int nxt = cur ^ 1;
        const bool pf = (t + 1 < 32);
        const uint32_t kcur_u = sb + 2*(AKV0 + (2*cur)*ASLAB);
        const uint32_t vcur_u = sb + 2*(AKV0 + (4 + 2*cur)*ASLAB);

        if (pf) {
            const size_t base = (size_t)((t + 1)*64)*DK_;
            #pragma unroll
            for (int i = 0; i < 2; i++) {
                const int idx = tid + i*256;
                const int row = idx >> 3, v = idx & 7;
                const uint32_t so = sb + 2*(AKV0 + row*APAD + v*8);
                const size_t  go = base + (size_t)row*DK_ + v*8;
                cpa16(so + 2*((2*nxt)*ASLAB),     Khi + go);
                cpa16(so + 2*((2*nxt+1)*ASLAB),   Klo + go);
                cpa16(so + 2*((4+2*nxt)*ASLAB),   Vhi + go);
                cpa16(so + 2*((4+2*nxt+1)*ASLAB), Vlo + go);
            }
            CPA_COMMIT();
        }

        float sacc[2][8][4];
        #pragma unroll
        for (int mi = 0; mi < 2; mi++)
            #pragma unroll
            for (int nj = 0; nj < 8; nj++)
                #pragma unroll
                for (int e = 0; e < 4; e++) sacc[mi][nj][e] = 0.0f;

        #pragma unroll
        for (int kk = 0; kk < 4; kk++) {
            uint32_t aqh[2][4], aql[2][4];
            #pragma unroll
            for (int mi = 0; mi < 2; mi++) {
                const int r   = wid*32 + mi*16 + (lane & 15);
                const int col = kk*16 + ((lane & 16) ? 8 : 0);
                ldsm4(aqh[mi], sb + 2*(0      + r*APAD + col));
                ldsm4(aql[mi], sb + 2*(AQSLAB + r*APAD + col));
            }
            #pragma unroll
            for (int jp = 0; jp < 4; jp++) {
                const int p   = lane >> 3;
                const int r   = jp*16 + ((p >= 2) ? 8 : 0) + (lane & 7);
                const int col = kk*16 + ((p & 1) ? 8 : 0);
                uint32_t th[4], tl[4];
                ldsm4(th, kcur_u + 2*(0*ASLAB + r*APAD + col));
                ldsm4(tl, kcur_u + 2*(1*ASLAB + r*APAD + col));
                #pragma unroll
                for (int mi = 0; mi < 2; mi++) {
                    mma16816(sacc[mi][2*jp],   aqh[mi], th);
                    mma16816(sacc[mi][2*jp],   aqh[mi], tl);
                    mma16816(sacc[mi][2*jp],   aql[mi], th);
                    mma16816(sacc[mi][2*jp+1], aqh[mi], th+2);
                    mma16816(sacc[mi][2*jp+1], aqh[mi], tl+2);
                    mma16816(sacc[mi][2*jp+1], aql[mi], th+2);
                }
            }
        }

        #pragma unroll
        for (int mi = 0; mi < 2; mi++) {
            if (msk[mi][0]) {
                #pragma unroll
                for (int nj = 0; nj < 8; nj++) { sacc[mi][nj][0] = NEGINF; sacc[mi][nj][1] = NEGINF; }
            }
            if (msk[mi][1]) {
                #pragma unroll
                for (int nj = 0; nj < 8; nj++) { sacc[mi][nj][2] = NEGINF; sacc[mi][nj][3] = NEGINF; }
            }

            float mx0 = -1e30f, mx1 = -1e30f;
            #pragma unroll
            for (int nj = 0; nj < 8; nj++) {
                mx0 = fmaxf(mx0, fmaxf(sacc[mi][nj][0], sacc[mi][nj][1]));
                mx1 = fmaxf(mx1, fmaxf(sacc[mi][nj][2], sacc[mi][nj][3]));
            }
            mx0 = fmaxf(mx0, __shfl_xor_sync(0xffffffffu, mx0, 1));
            mx0 = fmaxf(mx0, __shfl_xor_sync(0xffffffffu, mx0, 2));
            mx1 = fmaxf(mx1, __shfl_xor_sync(0xffffffffu, mx1, 1));
            mx1 = fmaxf(mx1, __shfl_xor_sync(0xffffffffu, mx1, 2));

            const float mn0 = fmaxf(mr[mi][0], mx0);
            const float mn1 = fmaxf(mr[mi][1], mx1);
            const float al0 = __expf(mr[mi][0] - mn0);
            const float al1 = __expf(mr[mi][1] - mn1);
            mr[mi][0] = mn0; mr[mi][1] = mn1;

            float rs0 = 0.0f, rs1 = 0.0f;
            #pragma unroll
            for (int nj = 0; nj < 8; nj++) {
                const float p0 = __expf(sacc[mi][nj][0] - mn0);
                const float p1 = __expf(sacc[mi][nj][1] - mn0);
                const float p2 = __expf(sacc[mi][nj][2] - mn1);
                const float p3 = __expf(sacc[mi][nj][3] - mn1);
                sacc[mi][nj][0] = p0; sacc[mi][nj][1] = p1;
                sacc[mi][nj][2] = p2; sacc[mi][nj][3] = p3;
                rs0 += p0 + p1; rs1 += p2 + p3;
            }
            rs0 += __shfl_xor_sync(0xffffffffu, rs0, 1);
            rs0 += __shfl_xor_sync(0xffffffffu, rs0, 2);
            rs1 += __shfl_xor_sync(0xffffffffu, rs1, 1);
            rs1 += __shfl_xor_sync(0xffffffffu, rs1, 2);
            lr[mi][0] = lr[mi][0]*al0 + rs0;
            lr[mi][1] = lr[mi][1]*al1 + rs1;

            #pragma unroll
            for (int nj = 0; nj < 8; nj++) {
                oacc[mi][nj][0] *= al0; oacc[mi][nj][1] *= al0;
                oacc[mi][nj][2] *= al1; oacc[mi][nj][3] *= al1;
            }
        }

        #pragma unroll
        for (int t4 = 0; t4 < 4; t4++) {
            uint32_t pa[2][4], pl[2][4];
            #pragma unroll
            for (int mi = 0; mi < 2; mi++) {
                const float p00 = sacc[mi][2*t4][0],   p01 = sacc[mi][2*t4][1];
                const float p02 = sacc[mi][2*t4][2],   p03 = sacc[mi][2*t4][3];
                const float p10 = sacc[mi][2*t4+1][0], p11 = sacc[mi][2*t4+1][1];
                const float p12 = sacc[mi][2*t4+1][2], p13 = sacc[mi][2*t4+1][3];
                pa[mi][0] = packbf(p00, p01); pa[mi][1] = packbf(p02, p03);
                pa[mi][2] = packbf(p10, p11); pa[mi][3] = packbf(p12, p13);
                pl[mi][0] = packbf(bfres(p00), bfres(p01)); pl[mi][1] = packbf(bfres(p02), bfres(p03));
                pl[mi][2] = packbf(bfres(p10), bfres(p11)); pl[mi][3] = packbf(bfres(p12), bfres(p13));
            }
            #pragma unroll
            for (int jp = 0; jp < 4; jp++) {
                const int p   = lane >> 3;
                const int r   = t4*16 + ((p & 1) ? 8 : 0) + (lane & 7);
                const int col = jp*16 + ((p >= 2) ? 8 : 0);
                uint32_t th[4], tl[4];
                ldsm4_t(th, vcur_u + 2*(0*ASLAB + r*APAD + col));
                ldsm4_t(tl, vcur_u + 2*(1*ASLAB + r*APAD + col));
                #pragma unroll
                for (int mi = 0; mi < 2; mi++) {
                    mma16816(oacc[mi][2*jp],   pa[mi], th);
                    mma16816(oacc[mi][2*jp],   pa[mi], tl);
                    mma16816(oacc[mi][2*jp],   pl[mi], th);
                    mma16816(oacc[mi][2*jp+1], pa[mi], th+2);
                    mma16816(oacc[mi][2*jp+1], pa[mi], tl+2);
                    mma16816(oacc[mi][2*jp+1], pl[mi], th+2);
                }
            }
        }

        if (pf) CPA_WAIT0();
        __syncthreads();
    }

    #pragma unroll
    for (int mi = 0; mi < 2; mi++) {
        const int qa = (mi == 0) ? qra0 : qra1;
        const float inv0 = 1.0f / lr[mi][0];
        const float inv1 = 1.0f / lr[mi][1];
        const size_t basea = ((size_t)(b*S_ + qa))*D_ + h*DK_;
        const size_t baseb = ((size_t)(b*S_ + qa + 8))*D_ + h*DK_;
        #pragma unroll
        for (int nj = 0; nj < 8; nj++) {
            const int dk = nj*8 + cc*2;
            const float v00 = oacc[mi][nj][0]*inv0, v01 = oacc[mi][nj][1]*inv0;
            const float v10 = oacc[mi][nj][2]*inv1, v11 = oacc[mi][nj][3]*inv1;
            *(uint32_t*)&g_att_hi[basea + dk] = packbf(v00, v01);
            *(uint32_t*)&g_att_lo[basea + dk] = packbf(bfres(v00), bfres(v01));
            *(uint32_t*)&g_att_hi[baseb + dk] = packbf(v10, v11);
            *(uint32_t*)&g_att_lo[baseb + dk] = packbf(bfres(v10), bfres(v11));
        }
    }
}

// ---------------------------------------------------------------------------
extern "C" void kernel_launch(void* const* d_in, const int* in_sizes, int n_in,
                              void* d_out, int out_size)
{
    const float* q    = (const float*)d_in[0];
    const float* k    = (const float*)d_in[1];
    const float* v    = (const float*)d_in[2];
    const int*   mask = (const int*)  d_in[3];
    const float* Wq   = (const float*)d_in[4];
    const float* bq   = (const float*)d_in[5];
    const float* Wk   = (const float*)d_in[6];
    const float* bk   = (const float*)d_in[7];
    const float* Wv   = (const float*)d_in[8];
    const float* bv   = (const float*)d_in[9];
    const float* Wo   = (const float*)d_in[10];
    const float* bo   = (const float*)d_in[11];
    float* out = (float*)d_out;

    static int configured = 0;
    if (!configured) {
        cudaFuncSetAttribute(qkv_mma_kernel, cudaFuncAttributeMaxDynamicSharedMemorySize, PROJ_SMEM);
        cudaFuncSetAttribute(out_mma_kernel, cudaFuncAttributeMaxDynamicSharedMemorySize, PROJ_SMEM);
        cudaFuncSetAttribute(attn_mma_kernel, cudaFuncAttributeMaxDynamicSharedMemorySize, ATT_SMEM);
        configured = 1;
    }

    // 1. QKV projections (128x256 tiles)
    qkv_mma_kernel<<<dim3(D_/256, M_/128, 3), 512, PROJ_SMEM>>>(
        q, k, v, Wq, bq, Wk, bk, Wv, bv);

    // 2. Attention (unchanged R9)
    attn_mma_kernel<<<dim3(S_/256, B_*H_), 256, ATT_SMEM>>>(mask);

    // 3. Output projection (128x256 tiles)
    out_mma_kernel<<<dim3(D_/256, M_/128), 512, PROJ_SMEM>>>(Wo, bo, out);
}